// round 15
// baseline (speedup 1.0000x reference)
#include <cuda_runtime.h>
#include <cuda_bf16.h>
#include <cstdint>

// ----------------------------------------------------------------------------
// NystromAttention: b=4, n=8192, dim=512, h=8, d=64, m=256, l=32, pinv=6, K=33
// R11: entire 24-GEMM Newton-Schulz chain fused into ONE persistent kernel
//      with software grid barriers (256 co-resident CTAs). fattn1 processes
//      256 rows/CTA (kL/W staged once per 2 row-blocks). Rest from R10.
// ----------------------------------------------------------------------------

#define B_   4
#define N_   8192
#define DIM_ 512
#define H_   8
#define D_   64
#define M_   256
#define L_   32
#define LDQKV 1536
#define NT_  (B_*N_)      // 32768
#define BH_  (B_*H_)      // 32

// ---------------- scratch (static device globals; no allocation) -------------
__device__ float g_qkv[(long long)NT_ * LDQKV];
__device__ float g_qL[BH_ * M_ * D_];
__device__ float g_kL[BH_ * M_ * D_];
__device__ float g_attn2[BH_ * M_ * M_];
__device__ float g_z0[BH_ * M_ * M_];
__device__ float g_z1[BH_ * M_ * M_];
__device__ float g_xz[BH_ * M_ * M_];
__device__ float g_t2[BH_ * M_ * M_];
__device__ float g_t3[BH_ * M_ * M_];
__device__ float g_av[BH_ * M_ * D_];
__device__ float g_W[BH_ * M_ * D_];
__device__ float g_outh[(long long)BH_ * N_ * D_];
__device__ float g_pre[(long long)NT_ * DIM_];
__device__ float g_avpart[8 * BH_ * M_ * D_];
__device__ float g_avstats[8 * BH_ * M_ * 2];
__device__ unsigned int g_bits[2];
__device__ unsigned int g_barc;

// ======================= mma.sync helpers =====================================
__device__ __forceinline__ uint32_t smem_u32(const void* p) {
    uint32_t a;
    asm("{ .reg .u64 tmp; cvta.to.shared.u64 tmp, %1; cvt.u32.u64 %0, tmp; }"
        : "=r"(a) : "l"(p));
    return a;
}
__device__ __forceinline__ void ldmx4(uint32_t* d, uint32_t addr) {
    asm volatile("ldmatrix.sync.aligned.m8n8.x4.shared.b16 {%0,%1,%2,%3}, [%4];"
                 : "=r"(d[0]), "=r"(d[1]), "=r"(d[2]), "=r"(d[3]) : "r"(addr));
}
__device__ __forceinline__ void mma16816(float* c, const uint32_t* a, const uint32_t* b) {
    asm volatile("mma.sync.aligned.m16n8k16.row.col.f32.bf16.bf16.f32 "
                 "{%0,%1,%2,%3}, {%4,%5,%6,%7}, {%8,%9}, {%0,%1,%2,%3};"
                 : "+f"(c[0]), "+f"(c[1]), "+f"(c[2]), "+f"(c[3])
                 : "r"(a[0]), "r"(a[1]), "r"(a[2]), "r"(a[3]), "r"(b[0]), "r"(b[1]));
}
__device__ __forceinline__ uint32_t pack2(__nv_bfloat16 a, __nv_bfloat16 b) {
    __nv_bfloat162 t; t.x = a; t.y = b;
    return *(uint32_t*)&t;
}
__device__ __forceinline__ void cvt_split4(float4 f, uint2& hi, uint2& lo) {
    __nv_bfloat16 h0 = __float2bfloat16(f.x), h1 = __float2bfloat16(f.y);
    __nv_bfloat16 h2 = __float2bfloat16(f.z), h3 = __float2bfloat16(f.w);
    __nv_bfloat16 l0 = __float2bfloat16(f.x - __bfloat162float(h0));
    __nv_bfloat16 l1 = __float2bfloat16(f.y - __bfloat162float(h1));
    __nv_bfloat16 l2 = __float2bfloat16(f.z - __bfloat162float(h2));
    __nv_bfloat16 l3 = __float2bfloat16(f.w - __bfloat162float(h3));
    hi.x = pack2(h0, h1); hi.y = pack2(h2, h3);
    lo.x = pack2(l0, l1); lo.y = pack2(l2, l3);
}
__device__ __forceinline__ uint2 cvt_hi4(float4 f) {
    uint2 hi;
    hi.x = pack2(__float2bfloat16(f.x), __float2bfloat16(f.y));
    hi.y = pack2(__float2bfloat16(f.z), __float2bfloat16(f.w));
    return hi;
}
__device__ __forceinline__ void split_pair(float a, float b, uint32_t& hi, uint32_t& lo) {
    __nv_bfloat16 ha = __float2bfloat16(a), hb = __float2bfloat16(b);
    hi = pack2(ha, hb);
    lo = pack2(__float2bfloat16(a - __bfloat162float(ha)),
               __float2bfloat16(b - __bfloat162float(hb)));
}

#define SPAD 40

// ======================= unified batched bf16-split GEMM ======================
template<int BN, int NTRM>
__global__ void __launch_bounds__(256) bgemm_kernel(
    const float* __restrict__ A, const float* __restrict__ B,
    float* __restrict__ C, const float* __restrict__ bias,
    int lda, int ldb, int ldc,
    long long aOut, long long aIn, long long bOut, long long bIn,
    long long cOut, long long cIn,
    int transB, int bmode, float alphaB, float scale,
    int kchunks, int kchunk_len, long long csplit)
{
    __shared__ __nv_bfloat16 As[NTRM == 3 ? 2 : 1][128][SPAD];
    __shared__ __nv_bfloat16 Bs[NTRM == 3 ? 2 : 1][BN][SPAD];

    constexpr int WN = BN / 2;
    constexpr int JN = WN / 8;
    constexpr int BJ = BN / 32;

    int tid = threadIdx.x, lane = tid & 31, wid = tid >> 5;
    int bb = blockIdx.z, ob = bb >> 3, ib = bb & 7;
    int ks = blockIdx.y % kchunks;
    int mtile = blockIdx.y / kchunks;
    int row0 = mtile << 7;
    int col0 = blockIdx.x * BN;

    const float* Ab = A + (long long)ob * aOut + (long long)ib * aIn;
    const float* Bb = B + (long long)ob * bOut + (long long)ib * bIn;
    float*       Cb = C + (long long)ob * cOut + (long long)ib * cIn + (long long)ks * csplit;

    int k_begin = ks * kchunk_len;
    int k_end = k_begin + kchunk_len;

    int wm = (wid >> 1) << 5;
    int wn = (wid & 1) * WN;

    float acc[2][JN][4];
#pragma unroll
    for (int i = 0; i < 2; ++i)
#pragma unroll
        for (int j = 0; j < JN; ++j)
#pragma unroll
            for (int q = 0; q < 4; ++q) acc[i][j][q] = 0.f;

    int lr = lane & 15, lk = (lane >> 4) << 3;

    int a_r = tid >> 3, a_kq = (tid & 7) << 2;
    int bt_r = tid >> 3, bt_kq = (tid & 7) << 2;
    int bn_kk = tid / (BN / 4), bn_nq = (tid % (BN / 4)) << 2;

    float4 aReg[4], bReg[BJ];

#pragma unroll
    for (int j = 0; j < 4; ++j)
        aReg[j] = *(const float4*)(Ab + (long long)(row0 + a_r + j * 32) * lda + k_begin + a_kq);
    if (transB) {
#pragma unroll
        for (int j = 0; j < BJ; ++j)
            bReg[j] = *(const float4*)(Bb + (long long)(col0 + bt_r + j * 32) * ldb + k_begin + bt_kq);
    } else {
#pragma unroll
        for (int j = 0; j < BJ; ++j)
            bReg[j] = *(const float4*)(Bb + (long long)(k_begin + bn_kk + j * (256 / (BN / 4))) * ldb + col0 + bn_nq);
    }

    for (int k0 = k_begin; k0 < k_end; k0 += 32) {
        __syncthreads();
#pragma unroll
        for (int j = 0; j < 4; ++j) {
            int r = a_r + j * 32;
            if (NTRM == 3) {
                uint2 hi, lo; cvt_split4(aReg[j], hi, lo);
                *(uint2*)&As[0][r][a_kq] = hi;
                *(uint2*)&As[NTRM - 2][r][a_kq] = lo;
            } else {
                *(uint2*)&As[0][r][a_kq] = cvt_hi4(aReg[j]);
            }
        }
        if (transB) {
#pragma unroll
            for (int j = 0; j < BJ; ++j) {
                int r = bt_r + j * 32;
                if (NTRM == 3) {
                    uint2 hi, lo; cvt_split4(bReg[j], hi, lo);
                    *(uint2*)&Bs[0][r][bt_kq] = hi;
                    *(uint2*)&Bs[NTRM - 2][r][bt_kq] = lo;
                } else {
                    *(uint2*)&Bs[0][r][bt_kq] = cvt_hi4(bReg[j]);
                }
            }
        } else {
#pragma unroll
            for (int j = 0; j < BJ; ++j) {
                int kk = bn_kk + j * (256 / (BN / 4));
                float4 f = bReg[j];
                if (bmode) {
                    int gk = k0 + kk, gn = col0 + bn_nq;
                    f.x = ((gk == gn + 0) ? alphaB : 0.f) - f.x;
                    f.y = ((gk == gn + 1) ? alphaB : 0.f) - f.y;
                    f.z = ((gk == gn + 2) ? alphaB : 0.f) - f.z;
                    f.w = ((gk == gn + 3) ? alphaB : 0.f) - f.w;
                }
                float e[4] = {f.x, f.y, f.z, f.w};
#pragma unroll
                for (int q = 0; q < 4; ++q) {
                    __nv_bfloat16 h = __float2bfloat16(e[q]);
                    Bs[0][bn_nq + q][kk] = h;
                    if (NTRM == 3)
                        Bs[NTRM - 2][bn_nq + q][kk] = __float2bfloat16(e[q] - __bfloat162float(h));
                }
            }
        }
        __syncthreads();

        int kn = k0 + 32;
        if (kn < k_end) {
#pragma unroll
            for (int j = 0; j < 4; ++j)
                aReg[j] = *(const float4*)(Ab + (long long)(row0 + a_r + j * 32) * lda + kn + a_kq);
            if (transB) {
#pragma unroll
                for (int j = 0; j < BJ; ++j)
                    bReg[j] = *(const float4*)(Bb + (long long)(col0 + bt_r + j * 32) * ldb + kn + bt_kq);
            } else {
#pragma unroll
                for (int j = 0; j < BJ; ++j)
                    bReg[j] = *(const float4*)(Bb + (long long)(kn + bn_kk + j * (256 / (BN / 4))) * ldb + col0 + bn_nq);
            }
        }

#pragma unroll
        for (int kss = 0; kss < 32; kss += 16) {
            uint32_t ahi[2][4], alo[2][4], bhi[JN][2], blo[JN][2];
#pragma unroll
            for (int im = 0; im < 2; ++im) {
                ldmx4(ahi[im], smem_u32(&As[0][wm + (im << 4) + lr][kss + lk]));
                if (NTRM == 3)
                    ldmx4(alo[im], smem_u32(&As[NTRM - 2][wm + (im << 4) + lr][kss + lk]));
            }
#pragma unroll
            for (int jb = 0; jb < JN / 2; ++jb) {
                uint32_t t[4];
                ldmx4(t, smem_u32(&Bs[0][wn + (jb << 4) + lr][kss + lk]));
                bhi[jb * 2][0] = t[0]; bhi[jb * 2 + 1][0] = t[1];
                bhi[jb * 2][1] = t[2]; bhi[jb * 2 + 1][1] = t[3];
                if (NTRM == 3) {
                    ldmx4(t, smem_u32(&Bs[NTRM - 2][wn + (jb << 4) + lr][kss + lk]));
                    blo[jb * 2][0] = t[0]; blo[jb * 2 + 1][0] = t[1];
                    blo[jb * 2][1] = t[2]; blo[jb * 2 + 1][1] = t[3];
                }
            }
#pragma unroll
            for (int im = 0; im < 2; ++im)
#pragma unroll
                for (int jn = 0; jn < JN; ++jn) {
                    mma16816(acc[im][jn], ahi[im], bhi[jn]);
                    if (NTRM == 3) {
                        mma16816(acc[im][jn], alo[im], bhi[jn]);
                        mma16816(acc[im][jn], ahi[im], blo[jn]);
                    }
                }
        }
    }

    int rr = lane >> 2, cc = (lane & 3) << 1;
#pragma unroll
    for (int im = 0; im < 2; ++im) {
        int grow = row0 + wm + (im << 4) + rr;
#pragma unroll
        for (int jn = 0; jn < JN; ++jn) {
            int gcol = col0 + wn + (jn << 3) + cc;
            float b0 = 0.f, b1 = 0.f;
            if (bias) { b0 = bias[gcol]; b1 = bias[gcol + 1]; }
            float2 v0 = make_float2(scale * acc[im][jn][0] + b0, scale * acc[im][jn][1] + b1);
            float2 v1 = make_float2(scale * acc[im][jn][2] + b0, scale * acc[im][jn][3] + b1);
            *(float2*)(Cb + (long long)grow * ldc + gcol) = v0;
            *(float2*)(Cb + (long long)(grow + 8) * ldc + gcol) = v1;
        }
    }
}

// ======================= persistent fused Newton-Schulz =======================
// 256 CTAs (co-resident), 24 GEMM phases with software grid barriers.
// Each phase: 256 tile-jobs (4 ntiles x 2 mtiles x 32 batches, BN=64, K=256).
__device__ __forceinline__ void gridbar(unsigned int target) {
    __threadfence();
    __syncthreads();
    if (threadIdx.x == 0) {
        atomicAdd(&g_barc, 1u);
        while (atomicAdd(&g_barc, 0u) < target) __nanosleep(64);
    }
    __syncthreads();
    __threadfence();
}

template<int NTRM>
__device__ __forceinline__ void gemm256_job(
    const float* __restrict__ Ab, const float* __restrict__ Bb, float* __restrict__ Cb,
    int row0, int col0, int bmode, float alphaB, float scale,
    __nv_bfloat16* As0, __nv_bfloat16* As1,
    __nv_bfloat16* Bs0, __nv_bfloat16* Bs1)
{
    int tid = threadIdx.x, lane = tid & 31, wid = tid >> 5;
    int wm = (wid >> 1) << 5;
    int wn = (wid & 1) << 5;       // WN = 32
    int lr = lane & 15, lk = (lane >> 4) << 3;

    float acc[2][4][4];
#pragma unroll
    for (int i = 0; i < 2; ++i)
#pragma unroll
        for (int j = 0; j < 4; ++j)
#pragma unroll
            for (int q = 0; q < 4; ++q) acc[i][j][q] = 0.f;

    int a_r = tid >> 3, a_kq = (tid & 7) << 2;
    int bn_kk = tid >> 4, bn_nq = (tid & 15) << 2;

    float4 aReg[4], bReg[2];
#pragma unroll
    for (int j = 0; j < 4; ++j)
        aReg[j] = *(const float4*)(Ab + (size_t)(row0 + a_r + j * 32) * 256 + a_kq);
#pragma unroll
    for (int j = 0; j < 2; ++j)
        bReg[j] = *(const float4*)(Bb + (size_t)(bn_kk + j * 16) * 256 + col0 + bn_nq);

    for (int k0 = 0; k0 < 256; k0 += 32) {
        __syncthreads();
#pragma unroll
        for (int j = 0; j < 4; ++j) {
            int r = a_r + j * 32;
            if (NTRM == 3) {
                uint2 hi, lo; cvt_split4(aReg[j], hi, lo);
                *(uint2*)&As0[r * SPAD + a_kq] = hi;
                *(uint2*)&As1[r * SPAD + a_kq] = lo;
            } else {
                *(uint2*)&As0[r * SPAD + a_kq] = cvt_hi4(aReg[j]);
            }
        }
#pragma unroll
        for (int j = 0; j < 2; ++j) {
            int kk = bn_kk + j * 16;
            float4 f = bReg[j];
            if (bmode) {
                int gk = k0 + kk, gn = col0 + bn_nq;
                f.x = ((gk == gn + 0) ? alphaB : 0.f) - f.x;
                f.y = ((gk == gn + 1) ? alphaB : 0.f) - f.y;
                f.z = ((gk == gn + 2) ? alphaB : 0.f) - f.z;
                f.w = ((gk == gn + 3) ? alphaB : 0.f) - f.w;
            }
            float e[4] = {f.x, f.y, f.z, f.w};
#pragma unroll
            for (int q = 0; q < 4; ++q) {
                __nv_bfloat16 h = __float2bfloat16(e[q]);
                Bs0[(bn_nq + q) * SPAD + kk] = h;
                if (NTRM == 3)
                    Bs1[(bn_nq + q) * SPAD + kk] = __float2bfloat16(e[q] - __bfloat162float(h));
            }
        }
        __syncthreads();

        int kn = k0 + 32;
        if (kn < 256) {
#pragma unroll
            for (int j = 0; j < 4; ++j)
                aReg[j] = *(const float4*)(Ab + (size_t)(row0 + a_r + j * 32) * 256 + kn + a_kq);
#pragma unroll
            for (int j = 0; j < 2; ++j)
                bReg[j] = *(const float4*)(Bb + (size_t)(kn + bn_kk + j * 16) * 256 + col0 + bn_nq);
        }

#pragma unroll
        for (int kss = 0; kss < 32; kss += 16) {
            uint32_t ahi[2][4], alo[2][4], bhi[4][2], blo[4][2];
#pragma unroll
            for (int im = 0; im < 2; ++im) {
                ldmx4(ahi[im], smem_u32(&As0[(wm + (im << 4) + lr) * SPAD + kss + lk]));
                if (NTRM == 3)
                    ldmx4(alo[im], smem_u32(&As1[(wm + (im << 4) + lr) * SPAD + kss + lk]));
            }
#pragma unroll
            for (int jb = 0; jb < 2; ++jb) {
                uint32_t t[4];
                ldmx4(t, smem_u32(&Bs0[(wn + (jb << 4) + lr) * SPAD + kss + lk]));
                bhi[jb * 2][0] = t[0]; bhi[jb * 2 + 1][0] = t[1];
                bhi[jb * 2][1] = t[2]; bhi[jb * 2 + 1][1] = t[3];
                if (NTRM == 3) {
                    ldmx4(t, smem_u32(&Bs1[(wn + (jb << 4) + lr) * SPAD + kss + lk]));
                    blo[jb * 2][0] = t[0]; blo[jb * 2 + 1][0] = t[1];
                    blo[jb * 2][1] = t[2]; blo[jb * 2 + 1][1] = t[3];
                }
            }
#pragma unroll
            for (int im = 0; im < 2; ++im)
#pragma unroll
                for (int jn = 0; jn < 4; ++jn) {
                    mma16816(acc[im][jn], ahi[im], bhi[jn]);
                    if (NTRM == 3) {
                        mma16816(acc[im][jn], alo[im], bhi[jn]);
                        mma16816(acc[im][jn], ahi[im], blo[jn]);
                    }
                }
        }
    }

    int rr = lane >> 2, cc = (lane & 3) << 1;
#pragma unroll
    for (int im = 0; im < 2; ++im) {
        int grow = row0 + wm + (im << 4) + rr;
#pragma unroll
        for (int jn = 0; jn < 4; ++jn) {
            int gcol = col0 + wn + (jn << 3) + cc;
            *(float2*)(Cb + (size_t)grow * 256 + gcol) =
                make_float2(scale * acc[im][jn][0], scale * acc[im][jn][1]);
            *(float2*)(Cb + (size_t)(grow + 8) * 256 + gcol) =
                make_float2(scale * acc[im][jn][2], scale * acc[im][jn][3]);
        }
    }
}

__global__ void __launch_bounds__(256) pinv_kernel(
    const float* __restrict__ attn2, float* __restrict__ z0, float* __restrict__ z1,
    float* __restrict__ xz, float* __restrict__ t2, float* __restrict__ t3)
{
    __shared__ __nv_bfloat16 As0[128 * SPAD], As1[128 * SPAD];
    __shared__ __nv_bfloat16 Bs0[64 * SPAD],  Bs1[64 * SPAD];

    int cta = blockIdx.x;          // 256 CTAs
    int bb = cta >> 3;
    int mtile = (cta >> 2) & 1;
    int ntile = cta & 3;
    int row0 = mtile << 7, col0 = ntile << 6;
    size_t off = (size_t)bb << 16;

    unsigned int step = 0;
    for (int it = 0; it < 6; ++it) {
        const float* zi = (it & 1) ? z1 : z0;
        float* zo = (it & 1) ? z0 : z1;
        if (it < 5) {
            gemm256_job<1>(attn2 + off, zi + off, xz + off, row0, col0, 0, 0.f, 1.f, As0, As1, Bs0, Bs1);
            gridbar(++step * 256u);
            gemm256_job<1>(xz + off, xz + off, t2 + off, row0, col0, 1, 7.f, 1.f, As0, As1, Bs0, Bs1);
            gridbar(++step * 256u);
            gemm256_job<1>(xz + off, t2 + off, t3 + off, row0, col0, 1, 15.f, 1.f, As0, As1, Bs0, Bs1);
            gridbar(++step * 256u);
            gemm256_job<1>(zi + off, t3 + off, zo + off, row0, col0, 1, 13.f, 0.25f, As0, As1, Bs0, Bs1);
            gridbar(++step * 256u);
        } else {
            gemm256_job<3>(attn2 + off, zi + off, xz + off, row0, col0, 0, 0.f, 1.f, As0, As1, Bs0, Bs1);
            gridbar(++step * 256u);
            gemm256_job<3>(xz + off, xz + off, t2 + off, row0, col0, 1, 7.f, 1.f, As0, As1, Bs0, Bs1);
            gridbar(++step * 256u);
            gemm256_job<3>(xz + off, t2 + off, t3 + off, row0, col0, 1, 15.f, 1.f, As0, As1, Bs0, Bs1);
            gridbar(++step * 256u);
            gemm256_job<3>(zi + off, t3 + off, zo + off, row0, col0, 1, 13.f, 0.25f, As0, As1, Bs0, Bs1);
        }
    }
}

// ======================= fused attn3 -> av (flash, split over keys) ===========
#define F3_SMEM 110592
__global__ void __launch_bounds__(256) fattn3_kernel(
    const float* __restrict__ qkv, const float* __restrict__ qL,
    float* __restrict__ part, float* __restrict__ stats)
{
    extern __shared__ char sm3[];
    __nv_bfloat16* Qh = (__nv_bfloat16*)sm3;              // [256][72]
    __nv_bfloat16* Ql = Qh + 256 * 72;
    __nv_bfloat16* Kh = (__nv_bfloat16*)(sm3 + 73728);    // [64][72]
    __nv_bfloat16* Kl = Kh + 64 * 72;
    __nv_bfloat16* Vh = (__nv_bfloat16*)(sm3 + 73728 + 18432); // [64 d][72 key]
    __nv_bfloat16* Vl = Vh + 64 * 72;

    int tid = threadIdx.x, lane = tid & 31, wid = tid >> 5;
    int bh = blockIdx.x, kc = blockIdx.y;
    int b = bh >> 3, h = bh & 7;
    int lr = lane & 15, lk = (lane >> 4) << 3;
    int m0 = wid << 5;

#pragma unroll
    for (int j = 0; j < 16; ++j) {
        int v = tid + (j << 8);
        int rr = v >> 4, c4 = (v & 15) << 2;
        float4 f = *(const float4*)(qL + (size_t)bh * 16384 + rr * 64 + c4);
        uint2 hi, lo; cvt_split4(f, hi, lo);
        *(uint2*)(Qh + rr * 72 + c4) = hi;
        *(uint2*)(Ql + rr * 72 + c4) = lo;
    }

    float O[2][8][4];
    float mst[2][2], lst[2][2];
#pragma unroll
    for (int mt = 0; mt < 2; ++mt) {
        mst[mt][0] = mst[mt][1] = -1e30f;
        lst[mt][0] = lst[mt][1] = 0.f;
#pragma unroll
        for (int j = 0; j < 8; ++j)
#pragma unroll
            for (int q = 0; q < 4; ++q) O[mt][j][q] = 0.f;
    }

    int s_rr = tid >> 4, s_c4 = (tid & 15) << 2;
    float4 kReg[4], vReg[4];
    {
        int key0 = kc << 10;
#pragma unroll
        for (int j = 0; j < 4; ++j) {
            int rr = s_rr + j * 16;
            kReg[j] = *(const float4*)(qkv + (size_t)(b * N_ + key0 + rr) * LDQKV + 512 + h * 64 + s_c4);
            vReg[j] = *(const float4*)(qkv + (size_t)(b * N_ + key0 + rr) * LDQKV + 1024 + h * 64 + s_c4);
        }
    }

    for (int c = 0; c < 16; ++c) {
        __syncthreads();
#pragma unroll
        for (int j = 0; j < 4; ++j) {
            int rr = s_rr + j * 16;
            uint2 hi, lo; cvt_split4(kReg[j], hi, lo);
            *(uint2*)(Kh + rr * 72 + s_c4) = hi;
            *(uint2*)(Kl + rr * 72 + s_c4) = lo;
            float e[4] = {vReg[j].x, vReg[j].y, vReg[j].z, vReg[j].w};
#pragma unroll
            for (int q = 0; q < 4; ++q) {
                __nv_bfloat16 hv = __float2bfloat16(e[q]);
                Vh[(s_c4 + q) * 72 + rr] = hv;
                Vl[(s_c4 + q) * 72 + rr] = __float2bfloat16(e[q] - __bfloat162float(hv));
            }
        }
        __syncthreads();

        if (c + 1 < 16) {
            int key0 = (kc << 10) + ((c + 1) << 6);
#pragma unroll
            for (int j = 0; j < 4; ++j) {
                int rr = s_rr + j * 16;
                kReg[j] = *(const float4*)(qkv + (size_t)(b * N_ + key0 + rr) * LDQKV + 512 + h * 64 + s_c4);
                vReg[j] = *(const float4*)(qkv + (size_t)(b * N_ + key0 + rr) * LDQKV + 1024 + h * 64 + s_c4);
            }
        }

#pragma unroll
        for (int mt = 0; mt < 2; ++mt) {
            float Lg[8][4];
#pragma unroll
            for (int j = 0; j < 8; ++j)
#pragma unroll
                for (int q = 0; q < 4; ++q) Lg[j][q] = 0.f;
#pragma unroll
            for (int ksx = 0; ksx < 4; ++ksx) {
                uint32_t qh[4], ql[4];
                ldmx4(qh, smem_u32(Qh + (m0 + mt * 16 + lr) * 72 + ksx * 16 + lk));
                ldmx4(ql, smem_u32(Ql + (m0 + mt * 16 + lr) * 72 + ksx * 16 + lk));
#pragma unroll
                for (int nb = 0; nb < 4; ++nb) {
                    uint32_t th[4], tl[4];
                    ldmx4(th, smem_u32(Kh + (nb * 16 + lr) * 72 + ksx * 16 + lk));
                    ldmx4(tl, smem_u32(Kl + (nb * 16 + lr) * 72 + ksx * 16 + lk));
                    uint32_t b0h[2] = {th[0], th[2]}, b1h[2] = {th[1], th[3]};
                    uint32_t b0l[2] = {tl[0], tl[2]}, b1l[2] = {tl[1], tl[3]};
                    mma16816(Lg[nb * 2], qh, b0h);
                    mma16816(Lg[nb * 2], ql, b0h);
                    mma16816(Lg[nb * 2], qh, b0l);
                    mma16816(Lg[nb * 2 + 1], qh, b1h);
                    mma16816(Lg[nb * 2 + 1], ql, b1h);
                    mma16816(Lg[nb * 2 + 1], qh, b1l);
                }
            }
            float cm0 = -1e30f, cm1 = -1e30f;
#pragma unroll
            for (int j = 0; j < 8; ++j) {
                cm0 = fmaxf(cm0, fmaxf(Lg[j][0], Lg[j][1]));
                cm1 = fmaxf(cm1, fmaxf(Lg[j][2], Lg[j][3]));
            }
            cm0 = fmaxf(cm0, __shfl_xor_sync(0xffffffffu, cm0, 1));
            cm0 = fmaxf(cm0, __shfl_xor_sync(0xffffffffu, cm0, 2));
            cm1 = fmaxf(cm1, __shfl_xor_sync(0xffffffffu, cm1, 1));
            cm1 = fmaxf(cm1, __shfl_xor_sync(0xffffffffu, cm1, 2));
            float mn0 = fmaxf(mst[mt][0], cm0);
            float mn1 = fmaxf(mst[mt][1], cm1);
            float r0 = __expf(mst[mt][0] - mn0);
            float r1 = __expf(mst[mt][1] - mn1);
            float s0 = 0.f, s1 = 0.f;
#pragma unroll
            for (int j = 0; j < 8; ++j) {
                Lg[j][0] = __expf(Lg[j][0] - mn0);
                Lg[j][1] = __expf(Lg[j][1] - mn0);
                Lg[j][2] = __expf(Lg[j][2] - mn1);
                Lg[j][3] = __expf(Lg[j][3] - mn1);
                s0 += Lg[j][0] + Lg[j][1];
                s1 += Lg[j][2] + Lg[j][3];
            }
            s0 += __shfl_xor_sync(0xffffffffu, s0, 1);
            s0 += __shfl_xor_sync(0xffffffffu, s0, 2);
            s1 += __shfl_xor_sync(0xffffffffu, s1, 1);
            s1 += __shfl_xor_sync(0xffffffffu, s1, 2);
            lst[mt][0] = lst[mt][0] * r0 + s0;
            lst[mt][1] = lst[mt][1] * r1 + s1;
            mst[mt][0] = mn0; mst[mt][1] = mn1;
#pragma unroll
            for (int j = 0; j < 8; ++j) {
                O[mt][j][0] *= r0; O[mt][j][1] *= r0;
                O[mt][j][2] *= r1; O[mt][j][3] *= r1;
            }
#pragma unroll
            for (int t = 0; t < 4; ++t) {
                uint32_t ph[4], pl[4];
                split_pair(Lg[2 * t][0],     Lg[2 * t][1],     ph[0], pl[0]);
                split_pair(Lg[2 * t][2],     Lg[2 * t][3],     ph[1], pl[1]);
                split_pair(Lg[2 * t + 1][0], Lg[2 * t + 1][1], ph[2], pl[2]);
                split_pair(Lg[2 * t + 1][2], Lg[2 * t + 1][3], ph[3], pl[3]);
#pragma unroll
                for (int nb = 0; nb < 4; ++nb) {
                    uint32_t th[4], tl[4];
                    ldmx4(th, smem_u32(Vh + (nb * 16 + lr) * 72 + t * 16 + lk));
                    ldmx4(tl, smem_u32(Vl + (nb * 16 + lr) * 72 + t * 16 + lk));
                    uint32_t b0h[2] = {th[0], th[2]}, b1h[2] = {th[1], th[3]};
                    uint32_t b0l[2] = {tl[0], tl[2]}, b1l[2] = {tl[1], tl[3]};
                    mma16816(O[mt][nb * 2], ph, b0h);
                    mma16816(O[mt][nb * 2], pl, b0h);
                    mma16816(O[mt][nb * 2], ph, b0l);
                    mma16816(O[mt][nb * 2 + 1], ph, b1h);
                    mma16816(O[mt][nb * 2 + 1], pl, b1h);
                    mma16816(O[mt][nb * 2 + 1], ph, b1l);
                }
            }
        }
    }

    int rr = lane >> 2, cc = (lane & 3) << 1;
    size_t pbase = ((size_t)kc * BH_ + bh) * (M_ * D_);
#pragma unroll
    for (int mt = 0; mt < 2; ++mt) {
        int row = m0 + mt * 16 + rr;
#pragma unroll
        for (int nj = 0; nj < 8; ++nj) {
            int col = nj * 8 + cc;
            *(float2*)(part + pbase + (size_t)row * 64 + col) =
                make_float2(O[mt][nj][0], O[mt][nj][1]);
            *(float2*)(part + pbase + (size_t)(row + 8) * 64 + col) =
                make_float2(O[mt][nj][2], O[mt][nj][3]);
        }
        if ((lane & 3) == 0) {
            size_t sb = ((size_t)kc * BH_ + bh) * M_;
            stats[(sb + row) * 2 + 0] = mst[mt][0];
            stats[(sb + row) * 2 + 1] = lst[mt][0];
            stats[(sb + row + 8) * 2 + 0] = mst[mt][1];
            stats[(sb + row + 8) * 2 + 1] = lst[mt][1];
        }
    }
}

__global__ void avreduce2_kernel(const float* __restrict__ part,
                                 const float* __restrict__ stats,
                                 float* __restrict__ av)
{
    int bh = blockIdx.x >> 8;
    int row = blockIdx.x & 255;
    int d = threadIdx.x;
    float M = -1e30f;
#pragma unroll
    for (int c = 0; c < 8; ++c)
        M = fmaxf(M, stats[(((size_t)c * BH_ + bh) * M_ + row) * 2]);
    float lt = 0.f, acc = 0.f;
#pragma unroll
    for (int c = 0; c < 8; ++c) {
        size_t sb = ((size_t)c * BH_ + bh) * M_ + row;
        float w = __expf(stats[sb * 2] - M);
        lt += w * stats[sb * 2 + 1];
        acc += w * part[(((size_t)c * BH_ + bh) * M_ + row) * 64 + d];
    }
    av[((size_t)bh * M_ + row) * 64 + d] = acc / lt;
}

// ======================= fused attn1 -> outh ==================================
// R11: 256 rows per CTA; kL/W staged once per two 128-row blocks.
#define F1_SMEM 178176
__global__ void __launch_bounds__(256) fattn1_kernel(
    const float* __restrict__ qkv, const float* __restrict__ kL,
    const float* __restrict__ Wz, float* __restrict__ outh)
{
    extern __shared__ char sm1[];
    __nv_bfloat16* Qh = (__nv_bfloat16*)sm1;               // [128][72]
    __nv_bfloat16* Ql = Qh + 128 * 72;
    __nv_bfloat16* Kh = (__nv_bfloat16*)(sm1 + 36864);     // [256][72]
    __nv_bfloat16* Kl = Kh + 256 * 72;
    __nv_bfloat16* Wh = (__nv_bfloat16*)(sm1 + 36864 + 73728); // [64][264]
    __nv_bfloat16* Wl = Wh + 64 * 264;

    int tid = threadIdx.x, lane = tid & 31, wid = tid >> 5;
    int bh = blockIdx.x;
    int b = bh >> 3, h = bh & 7;
    int i0base = blockIdx.y << 8;          // 256 rows per CTA
    int lr = lane & 15, lk = (lane >> 4) << 3;

    // stage kL + W once
#pragma unroll
    for (int j = 0; j < 16; ++j) {
        int v = tid + (j << 8);
        int rr = v >> 4, c4 = (v & 15) << 2;
        float4 f = *(const float4*)(kL + (size_t)bh * 16384 + rr * 64 + c4);
        uint2 hi, lo; cvt_split4(f, hi, lo);
        *(uint2*)(Kh + rr * 72 + c4) = hi;
        *(uint2*)(Kl + rr * 72 + c4) = lo;
    }
#pragma unroll
    for (int j = 0; j < 16; ++j) {
        int v = tid + (j << 8);
        int k = v >> 4, n4 = (v & 15) << 2;
        float4 f = *(const float4*)(Wz + (size_t)bh * 16384 + k * 64 + n4);
        float e[4] = {f.x, f.y, f.z, f.w};
#pragma unroll
        for (int q = 0; q < 4; ++q) {
            __nv_bfloat16 hv = __float2bfloat16(e[q]);
            Wh[(n4 + q) * 264 + k] = hv;
            Wl[(n4 + q) * 264 + k] = __float2bfloat16(e[q] - __bfloat162float(hv));
        }
    }

    for (int rblk = 0; rblk < 2; ++rblk) {
        int i0 = i0base + (rblk << 7);
        __syncthreads();   // previous block's Q reads done (also orders kL/W stage on rblk=0)
#pragma unroll
        for (int j = 0; j < 8; ++j) {
            int v = tid + (j << 8);
            int rr = v >> 4, c4 = (v & 15) << 2;
            float4 f = *(const float4*)(qkv + (size_t)(b * N_ + i0 + rr) * LDQKV + h * 64 + c4);
            f.x *= 0.125f; f.y *= 0.125f; f.z *= 0.125f; f.w *= 0.125f;
            uint2 hi, lo; cvt_split4(f, hi, lo);
            *(uint2*)(Qh + rr * 72 + c4) = hi;
            *(uint2*)(Ql + rr * 72 + c4) = lo;
        }
        __syncthreads();

        int m0 = wid << 4;
        float Lg[32][4];
#pragma unroll
        for (int j = 0; j < 32; ++j)
#pragma unroll
            for (int q = 0; q < 4; ++q) Lg[j][q] = 0.f;

#pragma unroll
        for (int ksx = 0; ksx < 4; ++ksx) {
            uint32_t qh[4], ql[4];
            ldmx4(qh, smem_u32(Qh + (m0 + lr) * 72 + ksx * 16 + lk));
            ldmx4(ql, smem_u32(Ql + (m0 + lr) * 72 + ksx * 16 + lk));
#pragma unroll
            for (int nb = 0; nb < 16; ++nb) {
                uint32_t th[4], tl[4];
                ldmx4(th, smem_u32(Kh + (nb * 16 + lr) * 72 + ksx * 16 + lk));
                ldmx4(tl, smem_u32(Kl + (nb * 16 + lr) * 72 + ksx * 16 + lk));
                uint32_t b0h[2] = {th[0], th[2]}, b1h[2] = {th[1], th[3]};
                uint32_t b0l[2] = {tl[0], tl[2]}, b1l[2] = {tl[1], tl[3]};
                mma16816(Lg[nb * 2], qh, b0h);
                mma16816(Lg[nb * 2], ql, b0h);
                mma16816(Lg[nb * 2], qh, b0l);
                mma16816(Lg[nb * 2 + 1], qh, b1h);
                mma16816(Lg[nb * 2 + 1], ql, b1h);
                mma16816(Lg[nb * 2 + 1], qh, b1l);
            }
        }

        float mx0 = -1e30f, mx1 = -1e30f;
#pragma unroll
        for (int j = 0; j < 32; ++j) {
            mx0 = fmaxf(mx0, fmaxf(Lg[j][0], Lg[j][1]));
            mx1 = fmaxf(mx1, fmaxf(Lg[j][2], Lg[j][3]));
        }
        mx0 = fmaxf(mx0, __shfl_xor_sync(0xffffffffu, mx0, 1));
        mx0 = fmaxf(mx0, __shfl_xor_sync(0xffffffffu, mx0, 2));
        mx1 = fmaxf(mx1, __shfl_xor_sync(0xffffffffu, mx1, 1));
        mx1 = fmaxf(mx1, __shfl_xor_sync(0xffffffffu, mx1, 2));
        float s0 = 0.f, s1 = 0.f;
#pragma unroll
        for (int j = 0; j < 32; ++j) {
            Lg[j][0] = __expf(Lg[j][0] - mx0);
            Lg[j][1] = __expf(Lg[j][1] - mx0);
            Lg[j][2] = __expf(Lg[j][2] - mx1);
            Lg[j][3] = __expf(Lg[j][3] - mx1);
            s0 += Lg[j][0] + Lg[j][1];
            s1 += Lg[j][2] + Lg[j][3];
        }
        s0 += __shfl_xor_sync(0xffffffffu, s0, 1);
        s0 += __shfl_xor_sync(0xffffffffu, s0, 2);
        s1 += __shfl_xor_sync(0xffffffffu, s1, 1);
        s1 += __shfl_xor_sync(0xffffffffu, s1, 2);
        float inv0 = 1.f / s0, inv1 = 1.f / s1;

        float O[8][4];
#pragma unroll
        for (int j = 0; j < 8; ++j)
#pragma unroll
            for (int q = 0; q < 4; ++q) O[j][q] = 0.f;

#pragma unroll
        for (int t = 0; t < 16; ++t) {
            uint32_t ph[4], pl[4];
            split_pair(Lg[2 * t][0] * inv0,     Lg[2 * t][1] * inv0,     ph[0], pl[0]);
            split_pair(Lg[2 * t][2] * inv1,     Lg[2 * t][3] * inv1,     ph[1], pl[1]);
            split_pair(Lg[2 * t + 1][0] * inv0, Lg[2 * t + 1][1] * inv0, ph[2], pl[2]);
            split_pair(Lg[2 * t + 1][2] * inv1, Lg[2 * t + 1][3] * inv1, ph[3], pl[3]);
#pragma unroll
            for (int nb = 0; nb < 4; ++nb) {
                uint32_t th[4], tl[4];
                ldmx4(th, smem_u32(Wh + (nb * 16 + lr) * 264 + t * 16 + lk));
                ldmx4(tl, smem_u32(Wl + (nb * 16 + lr) * 264 + t * 16 + lk));
                uint32_t b0h[2] = {th[0], th[2]}, b1h[2] = {th[1], th[3]};
                uint32_t b0l[2] = {tl[0], tl[2]}, b1l[2] = {tl[1], tl[3]};
                mma16816(O[nb * 2], ph, b0h);
                mma16816(O[nb * 2], pl, b0h);
                mma16816(O[nb * 2], ph, b0l);
                mma16816(O[nb * 2 + 1], ph, b1h);
                mma16816(O[nb * 2 + 1], pl, b1h);
                mma16816(O[nb * 2 + 1], ph, b1l);
            }
        }

        int rr = lane >> 2, cc = (lane & 3) << 1;
        size_t base = (size_t)bh * N_ + i0 + m0;
#pragma unroll
        for (int nj = 0; nj < 8; ++nj) {
            int col = nj * 8 + cc;
            *(float2*)(outh + (base + rr) * 64 + col) = make_float2(O[nj][0], O[nj][1]);
            *(float2*)(outh + (base + rr + 8) * 64 + col) = make_float2(O[nj][2], O[nj][3]);
        }
    }
}

// ---------------- landmarks ---------------------------------------------------
__global__ void landmarks_kernel(const float* __restrict__ qkv,
                                 float* __restrict__ qL, float* __restrict__ kL)
{
    int bh = blockIdx.x >> 8;
    int lm = blockIdx.x & 255;
    int b = bh >> 3, h = bh & 7;
    int d = threadIdx.x;
    long long base = ((long long)(b * N_ + lm * L_)) * LDQKV + h * D_ + d;
    float sq = 0.f, sk = 0.f;
#pragma unroll 4
    for (int t = 0; t < L_; t++) {
        sq += qkv[base + (long long)t * LDQKV];
        sk += qkv[base + (long long)t * LDQKV + 512];
    }
    long long o = ((long long)bh * M_ + lm) * D_ + d;
    qL[o] = sq * (0.125f / (float)L_);
    kL[o] = sk * (1.0f / (float)L_);
}

// ---------------- softmax (row length 256; for attn2) --------------------------
__global__ void softmax256_kernel(float* __restrict__ data)
{
    __shared__ float red[256];
    long long row = blockIdx.x;
    float* p = data + row * 256;
    int t = threadIdx.x;
    float v = p[t];
    red[t] = v; __syncthreads();
    for (int s = 128; s > 0; s >>= 1) { if (t < s) red[t] = fmaxf(red[t], red[t + s]); __syncthreads(); }
    float m = red[0]; __syncthreads();
    float e = __expf(v - m);
    red[t] = e; __syncthreads();
    for (int s = 128; s > 0; s >>= 1) { if (t < s) red[t] += red[t + s]; __syncthreads(); }
    p[t] = e * (1.f / red[0]);
}

// ---------------- pinv init ------------------------------------------------------
__global__ void init_bits_kernel(unsigned int* bits)
{
    if (threadIdx.x == 0) { bits[0] = __float_as_uint(1.0f); g_barc = 0u; }
    else bits[1] = 0u;
}

__global__ void colmax_kernel(const float* __restrict__ a, unsigned int* bits)
{
    __shared__ float red[256];
    int bb = blockIdx.x >> 8, j = blockIdx.x & 255;
    int t = threadIdx.x;
    red[t] = fabsf(a[((long long)bb << 16) + ((long long)t << 8) + j]);
    __syncthreads();
    for (int s = 128; s > 0; s >>= 1) { if (t < s) red[t] += red[t + s]; __syncthreads(); }
    if (t == 0) atomicMax(bits + 1, __float_as_uint(red[0]));
}

__global__ void zinit_kernel(const float* __restrict__ a, float* __restrict__ z,
                             const unsigned int* __restrict__ bits)
{
    float denom = __uint_as_float(bits[0]) * __uint_as_float(bits[1]) + 1e-12f;
    float inv = 1.f / denom;
    long long idx = (long long)blockIdx.x * 256 + threadIdx.x;
    long long bb = idx >> 16;
    int r = (int)(idx >> 8) & 255;
    int c = (int)idx & 255;
    z[idx] = a[(bb << 16) + ((long long)c << 8) + r] * inv;
}

// ---------------- depthwise conv residual + head-merge (rolling FIR) -----------
#define CCH 256
__global__ void __launch_bounds__(256) combine_kernel(
    const float* __restrict__ qkv, const float* __restrict__ outh,
    const float* __restrict__ convw, float* __restrict__ pre)
{
    int blk = blockIdx.x;
    int chunk = blk & 31;
    int hhalf = (blk >> 5) & 1;
    int b = blk >> 6;
    int h = hhalf * 4 + (threadIdx.x >> 6);
    int d = threadIdx.x & 63;
    int i0 = chunk * CCH;

    float cw[33];
#pragma unroll
    for (int t = 0; t < 33; ++t) cw[t] = convw[h * 33 + t];

    const float* vcol = qkv + 1024 + h * D_ + d;
    float w[33];
#pragma unroll
    for (int t = 0; t < 33; ++t) {
        int ii = i0 - 16 + t;
        w[t] = (ii >= 0 && ii < N_) ? vcol[(size_t)(b * N_ + ii) * LDQKV] : 0.f;
    }

    const float* orow = outh + (((size_t)(b * H_ + h)) * N_ + i0) * D_ + d;
    float* prow = pre + ((size_t)(b * N_ + i0)) * DIM_ + h * D_ + d;

    for (int i = 0; i < CCH; ++i) {
        float s = 0.f;
#pragma unroll
        for (int t = 0; t < 33; ++t) s += cw[t] * w[t];
        prow[(size_t)i * DIM_] = orow[(size_t)i * D_] + s;
#pragma unroll
        for (int t = 0; t < 32; ++t) w[t] = w[t + 1];
        int ii = i0 + i + 17;
        w[32] = (ii >= 0 && ii < N_) ? vcol[(size_t)(b * N_ + ii) * LDQKV] : 0.f;
    }
}

// ---------------- host side -----------------------------------------------------
struct GArgs {
    const float *A, *B; float* C; const float* bias;
    int lda, ldb, ldc;
    long long aO, aI, bO, bI, cO, cI;
    int transB, bmode; float alphaB, scale;
    int kchunks, klen; long long csplit;
};

template<int BN, int NTRM>
static inline void launch_bgemm(int M, int N, int batches, const GArgs& g, cudaStream_t st)
{
    dim3 grid(N / BN, (M / 128) * g.kchunks, batches);
    bgemm_kernel<BN, NTRM><<<grid, 256, 0, st>>>(g.A, g.B, g.C, g.bias, g.lda, g.ldb, g.ldc,
                                                 g.aO, g.aI, g.bO, g.bI, g.cO, g.cI,
                                                 g.transB, g.bmode, g.alphaB, g.scale,
                                                 g.kchunks, g.klen, g.csplit);
}

extern "C" void kernel_launch(void* const* d_in, const int* in_sizes, int n_in,
                              void* d_out, int out_size)
{
    const float* x     = (const float*)d_in[0];
    const float* Wqkv  = (const float*)d_in[1];
    const float* Wout  = (const float*)d_in[2];
    const float* bout  = (const float*)d_in[3];
    const float* convw = (const float*)d_in[4];
    float* out = (float*)d_out;

    float *qkv, *qL, *kL, *attn2, *z0, *z1, *xz, *t2, *t3, *av, *W, *outh, *pre;
    float *avpart, *avstats;
    unsigned int* bits;
    cudaGetSymbolAddress((void**)&qkv,    g_qkv);
    cudaGetSymbolAddress((void**)&qL,     g_qL);
    cudaGetSymbolAddress((void**)&kL,     g_kL);
    cudaGetSymbolAddress((void**)&attn2,  g_attn2);
    cudaGetSymbolAddress((void**)&z0,     g_z0);
    cudaGetSymbolAddress((void**)&z1,     g_z1);
    cudaGetSymbolAddress((void**)&xz,     g_xz);
    cudaGetSymbolAddress((void**)&t2,     g_t2);
    cudaGetSymbolAddress((void**)&t3,     g_t3);
    cudaGetSymbolAddress((void**)&av,     g_av);
    cudaGetSymbolAddress((void**)&W,      g_W);
    cudaGetSymbolAddress((void**)&outh,   g_outh);
    cudaGetSymbolAddress((void**)&pre,    g_pre);
    cudaGetSymbolAddress((void**)&avpart, g_avpart);
    cudaGetSymbolAddress((void**)&avstats,g_avstats);
    cudaGetSymbolAddress((void**)&bits,   g_bits);

    cudaFuncSetAttribute(fattn3_kernel, cudaFuncAttributeMaxDynamicSharedMemorySize, F3_SMEM);
    cudaFuncSetAttribute(fattn1_kernel, cudaFuncAttributeMaxDynamicSharedMemorySize, F1_SMEM);

    static cudaStream_t s1 = nullptr;
    static cudaEvent_t ev_land = nullptr, ev_z = nullptr;
    if (!s1) {
        cudaStreamCreateWithFlags(&s1, cudaStreamNonBlocking);
        cudaEventCreateWithFlags(&ev_land, cudaEventDisableTiming);
        cudaEventCreateWithFlags(&ev_z, cudaEventDisableTiming);
    }
    cudaStream_t s0 = 0;

    const long long MM = (long long)M_ * M_;
    const long long MD = (long long)M_ * D_;

    // 1) qkv = x @ Wqkv            [s0]
    { GArgs g{x, Wqkv, qkv, nullptr, 512, 1536, LDQKV,
              0,0, 0,0, 0,0, 0, 0, 0.f, 1.f, 1, 512, 0};
      launch_bgemm<128, 3>(NT_, 1536, 1, g, s0); }

    // 2) landmarks                 [s0]
    landmarks_kernel<<<BH_ * M_, 64, 0, s0>>>(qkv, qL, kL);
    cudaEventRecord(ev_land, s0);

    // ---- fork: pinv branch on s1 ----
    cudaStreamWaitEvent(s1, ev_land, 0);

    // attn2 logits + softmax
    { GArgs g{qL, kL, attn2, nullptr, 64, 64, M_,
              8*MD, MD, 8*MD, MD, 8*MM, MM, 1, 0, 0.f, 1.f, 1, 64, 0};
      launch_bgemm<64, 3>(M_, M_, BH_, g, s1); }
    softmax256_kernel<<<BH_ * M_, 256, 0, s1>>>(attn2);

    // pinv init (also resets grid barrier counter)
    init_bits_kernel<<<1, 2, 0, s1>>>(bits);
    colmax_kernel<<<BH_ * M_, 256, 0, s1>>>(attn2, bits);
    zinit_kernel<<<BH_ * M_, 256, 0, s1>>>(attn2, z0, bits);

    // fused 6-iteration Newton-Schulz (one persistent kernel, grid barriers)
    pinv_kernel<<<256, 256, 0, s1>>>(attn2, z0, z1, xz, t2, t3);
    cudaEventRecord(ev_z, s1);

    // ---- meanwhile on s0: fused attn3 -> av ----
    { dim3 grid(BH_, 8);
      fattn3_kernel<<<grid, 256, F3_SMEM, s0>>>(qkv, qL, avpart, avstats); }
    avreduce2_kernel<<<BH_ * M_, 64, 0, s0>>>(avpart, avstats, av);

    // ---- join ----
    cudaStreamWaitEvent(s0, ev_z, 0);

    // W = z @ av
    { GArgs g{z0, av, W, nullptr, M_, D_, D_,
              8*MM, MM, 8*MD, MD, 8*MD, MD, 0, 0, 0.f, 1.f, 1, M_, 0};
      launch_bgemm<64, 3>(M_, D_, BH_, g, s0); }

    // fused attn1 -> outh (256 rows per CTA)
    { dim3 grid(BH_, N_ / 256);
      fattn1_kernel<<<grid, 256, F1_SMEM, s0>>>(qkv, kL, W, outh); }

    // depthwise conv residual + merge heads (rolling FIR)
    combine_kernel<<<B_ * 2 * (N_ / CCH), 256, 0, s0>>>(qkv, outh, convw, pre);

    // out = pre @ Wout + bout
    { GArgs g{pre, Wout, out, bout, DIM_, DIM_, DIM_,
              0,0, 0,0, 0,0, 0, 0, 0.f, 1.f, 1, DIM_, 0};
      launch_bgemm<128, 3>(NT_, DIM_, 1, g, s0); }
}

// round 16
// speedup vs baseline: 1.0069x; 1.0069x over previous
#include <cuda_runtime.h>
#include <cuda_bf16.h>
#include <cstdint>

// ----------------------------------------------------------------------------
// NystromAttention: b=4, n=8192, dim=512, h=8, d=64, m=256, l=32, pinv=6, K=33
// R16: bgemm gets a 2-stage (double-buffered) smem pipeline via dynamic smem
//      (regs limit occupancy, so 80KB smem is free); softmax256 on shuffles.
//      Persistent pinv kernel untouched (co-residency safety). Rest from R15.
// ----------------------------------------------------------------------------

#define B_   4
#define N_   8192
#define DIM_ 512
#define H_   8
#define D_   64
#define M_   256
#define L_   32
#define LDQKV 1536
#define NT_  (B_*N_)      // 32768
#define BH_  (B_*H_)      // 32

// ---------------- scratch (static device globals; no allocation) -------------
__device__ float g_qkv[(long long)NT_ * LDQKV];
__device__ float g_qL[BH_ * M_ * D_];
__device__ float g_kL[BH_ * M_ * D_];
__device__ float g_attn2[BH_ * M_ * M_];
__device__ float g_z0[BH_ * M_ * M_];
__device__ float g_z1[BH_ * M_ * M_];
__device__ float g_xz[BH_ * M_ * M_];
__device__ float g_t2[BH_ * M_ * M_];
__device__ float g_t3[BH_ * M_ * M_];
__device__ float g_av[BH_ * M_ * D_];
__device__ float g_W[BH_ * M_ * D_];
__device__ float g_outh[(long long)BH_ * N_ * D_];
__device__ float g_pre[(long long)NT_ * DIM_];
__device__ float g_avpart[8 * BH_ * M_ * D_];
__device__ float g_avstats[8 * BH_ * M_ * 2];
__device__ unsigned int g_bits[2];
__device__ unsigned int g_barc;

// ======================= mma.sync helpers =====================================
__device__ __forceinline__ uint32_t smem_u32(const void* p) {
    uint32_t a;
    asm("{ .reg .u64 tmp; cvta.to.shared.u64 tmp, %1; cvt.u32.u64 %0, tmp; }"
        : "=r"(a) : "l"(p));
    return a;
}
__device__ __forceinline__ void ldmx4(uint32_t* d, uint32_t addr) {
    asm volatile("ldmatrix.sync.aligned.m8n8.x4.shared.b16 {%0,%1,%2,%3}, [%4];"
                 : "=r"(d[0]), "=r"(d[1]), "=r"(d[2]), "=r"(d[3]) : "r"(addr));
}
__device__ __forceinline__ void mma16816(float* c, const uint32_t* a, const uint32_t* b) {
    asm volatile("mma.sync.aligned.m16n8k16.row.col.f32.bf16.bf16.f32 "
                 "{%0,%1,%2,%3}, {%4,%5,%6,%7}, {%8,%9}, {%0,%1,%2,%3};"
                 : "+f"(c[0]), "+f"(c[1]), "+f"(c[2]), "+f"(c[3])
                 : "r"(a[0]), "r"(a[1]), "r"(a[2]), "r"(a[3]), "r"(b[0]), "r"(b[1]));
}
__device__ __forceinline__ uint32_t pack2(__nv_bfloat16 a, __nv_bfloat16 b) {
    __nv_bfloat162 t; t.x = a; t.y = b;
    return *(uint32_t*)&t;
}
__device__ __forceinline__ void cvt_split4(float4 f, uint2& hi, uint2& lo) {
    __nv_bfloat16 h0 = __float2bfloat16(f.x), h1 = __float2bfloat16(f.y);
    __nv_bfloat16 h2 = __float2bfloat16(f.z), h3 = __float2bfloat16(f.w);
    __nv_bfloat16 l0 = __float2bfloat16(f.x - __bfloat162float(h0));
    __nv_bfloat16 l1 = __float2bfloat16(f.y - __bfloat162float(h1));
    __nv_bfloat16 l2 = __float2bfloat16(f.z - __bfloat162float(h2));
    __nv_bfloat16 l3 = __float2bfloat16(f.w - __bfloat162float(h3));
    hi.x = pack2(h0, h1); hi.y = pack2(h2, h3);
    lo.x = pack2(l0, l1); lo.y = pack2(l2, l3);
}
__device__ __forceinline__ uint2 cvt_hi4(float4 f) {
    uint2 hi;
    hi.x = pack2(__float2bfloat16(f.x), __float2bfloat16(f.y));
    hi.y = pack2(__float2bfloat16(f.z), __float2bfloat16(f.w));
    return hi;
}
__device__ __forceinline__ void split_pair(float a, float b, uint32_t& hi, uint32_t& lo) {
    __nv_bfloat16 ha = __float2bfloat16(a), hb = __float2bfloat16(b);
    hi = pack2(ha, hb);
    lo = pack2(__float2bfloat16(a - __bfloat162float(ha)),
               __float2bfloat16(b - __bfloat162float(hb)));
}

#define SPAD 40

// ======================= unified batched bf16-split GEMM ======================
// R16: double-buffered smem stages (dynamic smem; regs limit occupancy so the
// extra smem is free). One __syncthreads per k-chunk.
template<int BN, int NTRM>
__global__ void __launch_bounds__(256) bgemm_kernel(
    const float* __restrict__ A, const float* __restrict__ B,
    float* __restrict__ C, const float* __restrict__ bias,
    int lda, int ldb, int ldc,
    long long aOut, long long aIn, long long bOut, long long bIn,
    long long cOut, long long cIn,
    int transB, int bmode, float alphaB, float scale,
    int kchunks, int kchunk_len, long long csplit)
{
    extern __shared__ __nv_bfloat16 db[];
    constexpr int TERMS = (NTRM == 3) ? 2 : 1;
    constexpr int ASZ = 128 * SPAD;
    constexpr int BSZ = BN * SPAD;
    constexpr int STG = TERMS * (ASZ + BSZ);

    constexpr int WN = BN / 2;
    constexpr int JN = WN / 8;
    constexpr int BJ = BN / 32;

    int tid = threadIdx.x, lane = tid & 31, wid = tid >> 5;
    int bb = blockIdx.z, ob = bb >> 3, ib = bb & 7;
    int ks = blockIdx.y % kchunks;
    int mtile = blockIdx.y / kchunks;
    int row0 = mtile << 7;
    int col0 = blockIdx.x * BN;

    const float* Ab = A + (long long)ob * aOut + (long long)ib * aIn;
    const float* Bb = B + (long long)ob * bOut + (long long)ib * bIn;
    float*       Cb = C + (long long)ob * cOut + (long long)ib * cIn + (long long)ks * csplit;

    int k_begin = ks * kchunk_len;
    int NC = kchunk_len >> 5;

    int wm = (wid >> 1) << 5;
    int wn = (wid & 1) * WN;

    float acc[2][JN][4];
#pragma unroll
    for (int i = 0; i < 2; ++i)
#pragma unroll
        for (int j = 0; j < JN; ++j)
#pragma unroll
            for (int q = 0; q < 4; ++q) acc[i][j][q] = 0.f;

    int lr = lane & 15, lk = (lane >> 4) << 3;

    int a_r = tid >> 3, a_kq = (tid & 7) << 2;
    int bt_r = tid >> 3, bt_kq = (tid & 7) << 2;
    int bn_kk = tid / (BN / 4), bn_nq = (tid % (BN / 4)) << 2;

    float4 aReg[4], bReg[BJ];

    auto ldg_tile = [&](int k0) {
#pragma unroll
        for (int j = 0; j < 4; ++j)
            aReg[j] = *(const float4*)(Ab + (long long)(row0 + a_r + j * 32) * lda + k0 + a_kq);
        if (transB) {
#pragma unroll
            for (int j = 0; j < BJ; ++j)
                bReg[j] = *(const float4*)(Bb + (long long)(col0 + bt_r + j * 32) * ldb + k0 + bt_kq);
        } else {
#pragma unroll
            for (int j = 0; j < BJ; ++j)
                bReg[j] = *(const float4*)(Bb + (long long)(k0 + bn_kk + j * (256 / (BN / 4))) * ldb + col0 + bn_nq);
        }
    };

    auto sts_tile = [&](int s, int k0tile) {
        __nv_bfloat16* As0 = db + s * STG;
        __nv_bfloat16* As1 = As0 + ASZ;
        __nv_bfloat16* Bs0 = db + s * STG + TERMS * ASZ;
        __nv_bfloat16* Bs1 = Bs0 + BSZ;
#pragma unroll
        for (int j = 0; j < 4; ++j) {
            int r = a_r + j * 32;
            if (NTRM == 3) {
                uint2 hi, lo; cvt_split4(aReg[j], hi, lo);
                *(uint2*)&As0[r * SPAD + a_kq] = hi;
                *(uint2*)&As1[r * SPAD + a_kq] = lo;
            } else {
                *(uint2*)&As0[r * SPAD + a_kq] = cvt_hi4(aReg[j]);
            }
        }
        if (transB) {
#pragma unroll
            for (int j = 0; j < BJ; ++j) {
                int r = bt_r + j * 32;
                if (NTRM == 3) {
                    uint2 hi, lo; cvt_split4(bReg[j], hi, lo);
                    *(uint2*)&Bs0[r * SPAD + bt_kq] = hi;
                    *(uint2*)&Bs1[r * SPAD + bt_kq] = lo;
                } else {
                    *(uint2*)&Bs0[r * SPAD + bt_kq] = cvt_hi4(bReg[j]);
                }
            }
        } else {
#pragma unroll
            for (int j = 0; j < BJ; ++j) {
                int kk = bn_kk + j * (256 / (BN / 4));
                float4 f = bReg[j];
                if (bmode) {
                    int gk = k0tile + kk, gn = col0 + bn_nq;
                    f.x = ((gk == gn + 0) ? alphaB : 0.f) - f.x;
                    f.y = ((gk == gn + 1) ? alphaB : 0.f) - f.y;
                    f.z = ((gk == gn + 2) ? alphaB : 0.f) - f.z;
                    f.w = ((gk == gn + 3) ? alphaB : 0.f) - f.w;
                }
                float e[4] = {f.x, f.y, f.z, f.w};
#pragma unroll
                for (int q = 0; q < 4; ++q) {
                    __nv_bfloat16 h = __float2bfloat16(e[q]);
                    Bs0[(bn_nq + q) * SPAD + kk] = h;
                    if (NTRM == 3)
                        Bs1[(bn_nq + q) * SPAD + kk] = __float2bfloat16(e[q] - __bfloat162float(h));
                }
            }
        }
    };

    auto compute_tile = [&](int s) {
        __nv_bfloat16* As0 = db + s * STG;
        __nv_bfloat16* As1 = As0 + ASZ;
        __nv_bfloat16* Bs0 = db + s * STG + TERMS * ASZ;
        __nv_bfloat16* Bs1 = Bs0 + BSZ;
#pragma unroll
        for (int kss = 0; kss < 32; kss += 16) {
            uint32_t ahi[2][4], alo[2][4], bhi[JN][2], blo[JN][2];
#pragma unroll
            for (int im = 0; im < 2; ++im) {
                ldmx4(ahi[im], smem_u32(&As0[(wm + (im << 4) + lr) * SPAD + kss + lk]));
                if (NTRM == 3)
                    ldmx4(alo[im], smem_u32(&As1[(wm + (im << 4) + lr) * SPAD + kss + lk]));
            }
#pragma unroll
            for (int jb = 0; jb < JN / 2; ++jb) {
                uint32_t t[4];
                ldmx4(t, smem_u32(&Bs0[(wn + (jb << 4) + lr) * SPAD + kss + lk]));
                bhi[jb * 2][0] = t[0]; bhi[jb * 2 + 1][0] = t[1];
                bhi[jb * 2][1] = t[2]; bhi[jb * 2 + 1][1] = t[3];
                if (NTRM == 3) {
                    ldmx4(t, smem_u32(&Bs1[(wn + (jb << 4) + lr) * SPAD + kss + lk]));
                    blo[jb * 2][0] = t[0]; blo[jb * 2 + 1][0] = t[1];
                    blo[jb * 2][1] = t[2]; blo[jb * 2 + 1][1] = t[3];
                }
            }
#pragma unroll
            for (int im = 0; im < 2; ++im)
#pragma unroll
                for (int jn = 0; jn < JN; ++jn) {
                    mma16816(acc[im][jn], ahi[im], bhi[jn]);
                    if (NTRM == 3) {
                        mma16816(acc[im][jn], alo[im], bhi[jn]);
                        mma16816(acc[im][jn], ahi[im], blo[jn]);
                    }
                }
        }
    };

    // prologue
    ldg_tile(k_begin);
    sts_tile(0, k_begin);
    __syncthreads();

    for (int c = 0; c < NC; ++c) {
        int kn = k_begin + ((c + 1) << 5);
        if (c + 1 < NC) ldg_tile(kn);
        compute_tile(c & 1);
        if (c + 1 < NC) {
            sts_tile((c + 1) & 1, kn);
            __syncthreads();
        }
    }

    int rr = lane >> 2, cc = (lane & 3) << 1;
#pragma unroll
    for (int im = 0; im < 2; ++im) {
        int grow = row0 + wm + (im << 4) + rr;
#pragma unroll
        for (int jn = 0; jn < JN; ++jn) {
            int gcol = col0 + wn + (jn << 3) + cc;
            float b0 = 0.f, b1 = 0.f;
            if (bias) { b0 = bias[gcol]; b1 = bias[gcol + 1]; }
            float2 v0 = make_float2(scale * acc[im][jn][0] + b0, scale * acc[im][jn][1] + b1);
            float2 v1 = make_float2(scale * acc[im][jn][2] + b0, scale * acc[im][jn][3] + b1);
            *(float2*)(Cb + (long long)grow * ldc + gcol) = v0;
            *(float2*)(Cb + (long long)(grow + 8) * ldc + gcol) = v1;
        }
    }
}

// ======================= persistent fused Newton-Schulz (unchanged) ===========
__device__ __forceinline__ void gridbar(unsigned int target) {
    __threadfence();
    __syncthreads();
    if (threadIdx.x == 0) {
        atomicAdd(&g_barc, 1u);
        while (atomicAdd(&g_barc, 0u) < target) __nanosleep(64);
    }
    __syncthreads();
    __threadfence();
}

template<int NTRM>
__device__ __forceinline__ void gemm256_job(
    const float* __restrict__ Ab, const float* __restrict__ Bb, float* __restrict__ Cb,
    int row0, int col0, int bmode, float alphaB, float scale,
    __nv_bfloat16* As0, __nv_bfloat16* As1,
    __nv_bfloat16* Bs0, __nv_bfloat16* Bs1)
{
    int tid = threadIdx.x, lane = tid & 31, wid = tid >> 5;
    int wm = (wid >> 1) << 5;
    int wn = (wid & 1) << 5;
    int lr = lane & 15, lk = (lane >> 4) << 3;

    float acc[2][4][4];
#pragma unroll
    for (int i = 0; i < 2; ++i)
#pragma unroll
        for (int j = 0; j < 4; ++j)
#pragma unroll
            for (int q = 0; q < 4; ++q) acc[i][j][q] = 0.f;

    int a_r = tid >> 3, a_kq = (tid & 7) << 2;
    int bn_kk = tid >> 4, bn_nq = (tid & 15) << 2;

    float4 aReg[4], bReg[2];
#pragma unroll
    for (int j = 0; j < 4; ++j)
        aReg[j] = *(const float4*)(Ab + (size_t)(row0 + a_r + j * 32) * 256 + a_kq);
#pragma unroll
    for (int j = 0; j < 2; ++j)
        bReg[j] = *(const float4*)(Bb + (size_t)(bn_kk + j * 16) * 256 + col0 + bn_nq);

    for (int k0 = 0; k0 < 256; k0 += 32) {
        __syncthreads();
#pragma unroll
        for (int j = 0; j < 4; ++j) {
            int r = a_r + j * 32;
            if (NTRM == 3) {
                uint2 hi, lo; cvt_split4(aReg[j], hi, lo);
                *(uint2*)&As0[r * SPAD + a_kq] = hi;
                *(uint2*)&As1[r * SPAD + a_kq] = lo;
            } else {
                *(uint2*)&As0[r * SPAD + a_kq] = cvt_hi4(aReg[j]);
            }
        }
#pragma unroll
        for (int j = 0; j < 2; ++j) {
            int kk = bn_kk + j * 16;
            float4 f = bReg[j];
            if (bmode) {
                int gk = k0 + kk, gn = col0 + bn_nq;
                f.x = ((gk == gn + 0) ? alphaB : 0.f) - f.x;
                f.y = ((gk == gn + 1) ? alphaB : 0.f) - f.y;
                f.z = ((gk == gn + 2) ? alphaB : 0.f) - f.z;
                f.w = ((gk == gn + 3) ? alphaB : 0.f) - f.w;
            }
            float e[4] = {f.x, f.y, f.z, f.w};
#pragma unroll
            for (int q = 0; q < 4; ++q) {
                __nv_bfloat16 h = __float2bfloat16(e[q]);
                Bs0[(bn_nq + q) * SPAD + kk] = h;
                if (NTRM == 3)
                    Bs1[(bn_nq + q) * SPAD + kk] = __float2bfloat16(e[q] - __bfloat162float(h));
            }
        }
        __syncthreads();

        int kn = k0 + 32;
        if (kn < 256) {
#pragma unroll
            for (int j = 0; j < 4; ++j)
                aReg[j] = *(const float4*)(Ab + (size_t)(row0 + a_r + j * 32) * 256 + kn + a_kq);
#pragma unroll
            for (int j = 0; j < 2; ++j)
                bReg[j] = *(const float4*)(Bb + (size_t)(kn + bn_kk + j * 16) * 256 + col0 + bn_nq);
        }

#pragma unroll
        for (int kss = 0; kss < 32; kss += 16) {
            uint32_t ahi[2][4], alo[2][4], bhi[4][2], blo[4][2];
#pragma unroll
            for (int im = 0; im < 2; ++im) {
                ldmx4(ahi[im], smem_u32(&As0[(wm + (im << 4) + lr) * SPAD + kss + lk]));
                if (NTRM == 3)
                    ldmx4(alo[im], smem_u32(&As1[(wm + (im << 4) + lr) * SPAD + kss + lk]));
            }
#pragma unroll
            for (int jb = 0; jb < 2; ++jb) {
                uint32_t t[4];
                ldmx4(t, smem_u32(&Bs0[(wn + (jb << 4) + lr) * SPAD + kss + lk]));
                bhi[jb * 2][0] = t[0]; bhi[jb * 2 + 1][0] = t[1];
                bhi[jb * 2][1] = t[2]; bhi[jb * 2 + 1][1] = t[3];
                if (NTRM == 3) {
                    ldmx4(t, smem_u32(&Bs1[(wn + (jb << 4) + lr) * SPAD + kss + lk]));
                    blo[jb * 2][0] = t[0]; blo[jb * 2 + 1][0] = t[1];
                    blo[jb * 2][1] = t[2]; blo[jb * 2 + 1][1] = t[3];
                }
            }
#pragma unroll
            for (int im = 0; im < 2; ++im)
#pragma unroll
                for (int jn = 0; jn < 4; ++jn) {
                    mma16816(acc[im][jn], ahi[im], bhi[jn]);
                    if (NTRM == 3) {
                        mma16816(acc[im][jn], alo[im], bhi[jn]);
                        mma16816(acc[im][jn], ahi[im], blo[jn]);
                    }
                }
        }
    }

    int rr = lane >> 2, cc = (lane & 3) << 1;
#pragma unroll
    for (int im = 0; im < 2; ++im) {
        int grow = row0 + wm + (im << 4) + rr;
#pragma unroll
        for (int jn = 0; jn < 4; ++jn) {
            int gcol = col0 + wn + (jn << 3) + cc;
            *(float2*)(Cb + (size_t)grow * 256 + gcol) =
                make_float2(scale * acc[im][jn][0], scale * acc[im][jn][1]);
            *(float2*)(Cb + (size_t)(grow + 8) * 256 + gcol) =
                make_float2(scale * acc[im][jn][2], scale * acc[im][jn][3]);
        }
    }
}

__global__ void __launch_bounds__(256) pinv_kernel(
    const float* __restrict__ attn2, float* __restrict__ z0, float* __restrict__ z1,
    float* __restrict__ xz, float* __restrict__ t2, float* __restrict__ t3)
{
    __shared__ __nv_bfloat16 As0[128 * SPAD], As1[128 * SPAD];
    __shared__ __nv_bfloat16 Bs0[64 * SPAD],  Bs1[64 * SPAD];

    int cta = blockIdx.x;
    int bb = cta >> 3;
    int mtile = (cta >> 2) & 1;
    int ntile = cta & 3;
    int row0 = mtile << 7, col0 = ntile << 6;
    size_t off = (size_t)bb << 16;

    unsigned int step = 0;
    for (int it = 0; it < 6; ++it) {
        const float* zi = (it & 1) ? z1 : z0;
        float* zo = (it & 1) ? z0 : z1;
        if (it < 5) {
            gemm256_job<1>(attn2 + off, zi + off, xz + off, row0, col0, 0, 0.f, 1.f, As0, As1, Bs0, Bs1);
            gridbar(++step * 256u);
            gemm256_job<1>(xz + off, xz + off, t2 + off, row0, col0, 1, 7.f, 1.f, As0, As1, Bs0, Bs1);
            gridbar(++step * 256u);
            gemm256_job<1>(xz + off, t2 + off, t3 + off, row0, col0, 1, 15.f, 1.f, As0, As1, Bs0, Bs1);
            gridbar(++step * 256u);
            gemm256_job<1>(zi + off, t3 + off, zo + off, row0, col0, 1, 13.f, 0.25f, As0, As1, Bs0, Bs1);
            gridbar(++step * 256u);
        } else {
            gemm256_job<3>(attn2 + off, zi + off, xz + off, row0, col0, 0, 0.f, 1.f, As0, As1, Bs0, Bs1);
            gridbar(++step * 256u);
            gemm256_job<3>(xz + off, xz + off, t2 + off, row0, col0, 1, 7.f, 1.f, As0, As1, Bs0, Bs1);
            gridbar(++step * 256u);
            gemm256_job<3>(xz + off, t2 + off, t3 + off, row0, col0, 1, 15.f, 1.f, As0, As1, Bs0, Bs1);
            gridbar(++step * 256u);
            gemm256_job<3>(zi + off, t3 + off, zo + off, row0, col0, 1, 13.f, 0.25f, As0, As1, Bs0, Bs1);
        }
    }
}

// ======================= fused attn3 -> av (flash, split over keys) ===========
#define F3_SMEM 110592
__global__ void __launch_bounds__(256) fattn3_kernel(
    const float* __restrict__ qkv, const float* __restrict__ qL,
    float* __restrict__ part, float* __restrict__ stats)
{
    extern __shared__ char sm3[];
    __nv_bfloat16* Qh = (__nv_bfloat16*)sm3;              // [256][72]
    __nv_bfloat16* Ql = Qh + 256 * 72;
    __nv_bfloat16* Kh = (__nv_bfloat16*)(sm3 + 73728);    // [64][72]
    __nv_bfloat16* Kl = Kh + 64 * 72;
    __nv_bfloat16* Vh = (__nv_bfloat16*)(sm3 + 73728 + 18432); // [64 d][72 key]
    __nv_bfloat16* Vl = Vh + 64 * 72;

    int tid = threadIdx.x, lane = tid & 31, wid = tid >> 5;
    int bh = blockIdx.x, kc = blockIdx.y;
    int b = bh >> 3, h = bh & 7;
    int lr = lane & 15, lk = (lane >> 4) << 3;
    int m0 = wid << 5;

#pragma unroll
    for (int j = 0; j < 16; ++j) {
        int v = tid + (j << 8);
        int rr = v >> 4, c4 = (v & 15) << 2;
        float4 f = *(const float4*)(qL + (size_t)bh * 16384 + rr * 64 + c4);
        uint2 hi, lo; cvt_split4(f, hi, lo);
        *(uint2*)(Qh + rr * 72 + c4) = hi;
        *(uint2*)(Ql + rr * 72 + c4) = lo;
    }

    float O[2][8][4];
    float mst[2][2], lst[2][2];
#pragma unroll
    for (int mt = 0; mt < 2; ++mt) {
        mst[mt][0] = mst[mt][1] = -1e30f;
        lst[mt][0] = lst[mt][1] = 0.f;
#pragma unroll
        for (int j = 0; j < 8; ++j)
#pragma unroll
            for (int q = 0; q < 4; ++q) O[mt][j][q] = 0.f;
    }

    int s_rr = tid >> 4, s_c4 = (tid & 15) << 2;
    float4 kReg[4], vReg[4];
    {
        int key0 = kc << 10;
#pragma unroll
        for (int j = 0; j < 4; ++j) {
            int rr = s_rr + j * 16;
            kReg[j] = *(const float4*)(qkv + (size_t)(b * N_ + key0 + rr) * LDQKV + 512 + h * 64 + s_c4);
            vReg[j] = *(const float4*)(qkv + (size_t)(b * N_ + key0 + rr) * LDQKV + 1024 + h * 64 + s_c4);
        }
    }

    for (int c = 0; c < 16; ++c) {
        __syncthreads();
#pragma unroll
        for (int j = 0; j < 4; ++j) {
            int rr = s_rr + j * 16;
            uint2 hi, lo; cvt_split4(kReg[j], hi, lo);
            *(uint2*)(Kh + rr * 72 + s_c4) = hi;
            *(uint2*)(Kl + rr * 72 + s_c4) = lo;
            float e[4] = {vReg[j].x, vReg[j].y, vReg[j].z, vReg[j].w};
#pragma unroll
            for (int q = 0; q < 4; ++q) {
                __nv_bfloat16 hv = __float2bfloat16(e[q]);
                Vh[(s_c4 + q) * 72 + rr] = hv;
                Vl[(s_c4 + q) * 72 + rr] = __float2bfloat16(e[q] - __bfloat162float(hv));
            }
        }
        __syncthreads();

        if (c + 1 < 16) {
            int key0 = (kc << 10) + ((c + 1) << 6);
#pragma unroll
            for (int j = 0; j < 4; ++j) {
                int rr = s_rr + j * 16;
                kReg[j] = *(const float4*)(qkv + (size_t)(b * N_ + key0 + rr) * LDQKV + 512 + h * 64 + s_c4);
                vReg[j] = *(const float4*)(qkv + (size_t)(b * N_ + key0 + rr) * LDQKV + 1024 + h * 64 + s_c4);
            }
        }

#pragma unroll
        for (int mt = 0; mt < 2; ++mt) {
            float Lg[8][4];
#pragma unroll
            for (int j = 0; j < 8; ++j)
#pragma unroll
                for (int q = 0; q < 4; ++q) Lg[j][q] = 0.f;
#pragma unroll
            for (int ksx = 0; ksx < 4; ++ksx) {
                uint32_t qh[4], ql[4];
                ldmx4(qh, smem_u32(Qh + (m0 + mt * 16 + lr) * 72 + ksx * 16 + lk));
                ldmx4(ql, smem_u32(Ql + (m0 + mt * 16 + lr) * 72 + ksx * 16 + lk));
#pragma unroll
                for (int nb = 0; nb < 4; ++nb) {
                    uint32_t th[4], tl[4];
                    ldmx4(th, smem_u32(Kh + (nb * 16 + lr) * 72 + ksx * 16 + lk));
                    ldmx4(tl, smem_u32(Kl + (nb * 16 + lr) * 72 + ksx * 16 + lk));
                    uint32_t b0h[2] = {th[0], th[2]}, b1h[2] = {th[1], th[3]};
                    uint32_t b0l[2] = {tl[0], tl[2]}, b1l[2] = {tl[1], tl[3]};
                    mma16816(Lg[nb * 2], qh, b0h);
                    mma16816(Lg[nb * 2], ql, b0h);
                    mma16816(Lg[nb * 2], qh, b0l);
                    mma16816(Lg[nb * 2 + 1], qh, b1h);
                    mma16816(Lg[nb * 2 + 1], ql, b1h);
                    mma16816(Lg[nb * 2 + 1], qh, b1l);
                }
            }
            float cm0 = -1e30f, cm1 = -1e30f;
#pragma unroll
            for (int j = 0; j < 8; ++j) {
                cm0 = fmaxf(cm0, fmaxf(Lg[j][0], Lg[j][1]));
                cm1 = fmaxf(cm1, fmaxf(Lg[j][2], Lg[j][3]));
            }
            cm0 = fmaxf(cm0, __shfl_xor_sync(0xffffffffu, cm0, 1));
            cm0 = fmaxf(cm0, __shfl_xor_sync(0xffffffffu, cm0, 2));
            cm1 = fmaxf(cm1, __shfl_xor_sync(0xffffffffu, cm1, 1));
            cm1 = fmaxf(cm1, __shfl_xor_sync(0xffffffffu, cm1, 2));
            float mn0 = fmaxf(mst[mt][0], cm0);
            float mn1 = fmaxf(mst[mt][1], cm1);
            float r0 = __expf(mst[mt][0] - mn0);
            float r1 = __expf(mst[mt][1] - mn1);
            float s0 = 0.f, s1 = 0.f;
#pragma unroll
            for (int j = 0; j < 8; ++j) {
                Lg[j][0] = __expf(Lg[j][0] - mn0);
                Lg[j][1] = __expf(Lg[j][1] - mn0);
                Lg[j][2] = __expf(Lg[j][2] - mn1);
                Lg[j][3] = __expf(Lg[j][3] - mn1);
                s0 += Lg[j][0] + Lg[j][1];
                s1 += Lg[j][2] + Lg[j][3];
            }
            s0 += __shfl_xor_sync(0xffffffffu, s0, 1);
            s0 += __shfl_xor_sync(0xffffffffu, s0, 2);
            s1 += __shfl_xor_sync(0xffffffffu, s1, 1);
            s1 += __shfl_xor_sync(0xffffffffu, s1, 2);
            lst[mt][0] = lst[mt][0] * r0 + s0;
            lst[mt][1] = lst[mt][1] * r1 + s1;
            mst[mt][0] = mn0; mst[mt][1] = mn1;
#pragma unroll
            for (int j = 0; j < 8; ++j) {
                O[mt][j][0] *= r0; O[mt][j][1] *= r0;
                O[mt][j][2] *= r1; O[mt][j][3] *= r1;
            }
#pragma unroll
            for (int t = 0; t < 4; ++t) {
                uint32_t ph[4], pl[4];
                split_pair(Lg[2 * t][0],     Lg[2 * t][1],     ph[0], pl[0]);
                split_pair(Lg[2 * t][2],     Lg[2 * t][3],     ph[1], pl[1]);
                split_pair(Lg[2 * t + 1][0], Lg[2 * t + 1][1], ph[2], pl[2]);
                split_pair(Lg[2 * t + 1][2], Lg[2 * t + 1][3], ph[3], pl[3]);
#pragma unroll
                for (int nb = 0; nb < 4; ++nb) {
                    uint32_t th[4], tl[4];
                    ldmx4(th, smem_u32(Vh + (nb * 16 + lr) * 72 + t * 16 + lk));
                    ldmx4(tl, smem_u32(Vl + (nb * 16 + lr) * 72 + t * 16 + lk));
                    uint32_t b0h[2] = {th[0], th[2]}, b1h[2] = {th[1], th[3]};
                    uint32_t b0l[2] = {tl[0], tl[2]}, b1l[2] = {tl[1], tl[3]};
                    mma16816(O[mt][nb * 2], ph, b0h);
                    mma16816(O[mt][nb * 2], pl, b0h);
                    mma16816(O[mt][nb * 2], ph, b0l);
                    mma16816(O[mt][nb * 2 + 1], ph, b1h);
                    mma16816(O[mt][nb * 2 + 1], pl, b1h);
                    mma16816(O[mt][nb * 2 + 1], ph, b1l);
                }
            }
        }
    }

    int rr = lane >> 2, cc = (lane & 3) << 1;
    size_t pbase = ((size_t)kc * BH_ + bh) * (M_ * D_);
#pragma unroll
    for (int mt = 0; mt < 2; ++mt) {
        int row = m0 + mt * 16 + rr;
#pragma unroll
        for (int nj = 0; nj < 8; ++nj) {
            int col = nj * 8 + cc;
            *(float2*)(part + pbase + (size_t)row * 64 + col) =
                make_float2(O[mt][nj][0], O[mt][nj][1]);
            *(float2*)(part + pbase + (size_t)(row + 8) * 64 + col) =
                make_float2(O[mt][nj][2], O[mt][nj][3]);
        }
        if ((lane & 3) == 0) {
            size_t sb = ((size_t)kc * BH_ + bh) * M_;
            stats[(sb + row) * 2 + 0] = mst[mt][0];
            stats[(sb + row) * 2 + 1] = lst[mt][0];
            stats[(sb + row + 8) * 2 + 0] = mst[mt][1];
            stats[(sb + row + 8) * 2 + 1] = lst[mt][1];
        }
    }
}

__global__ void avreduce2_kernel(const float* __restrict__ part,
                                 const float* __restrict__ stats,
                                 float* __restrict__ av)
{
    int bh = blockIdx.x >> 8;
    int row = blockIdx.x & 255;
    int d = threadIdx.x;
    float M = -1e30f;
#pragma unroll
    for (int c = 0; c < 8; ++c)
        M = fmaxf(M, stats[(((size_t)c * BH_ + bh) * M_ + row) * 2]);
    float lt = 0.f, acc = 0.f;
#pragma unroll
    for (int c = 0; c < 8; ++c) {
        size_t sb = ((size_t)c * BH_ + bh) * M_ + row;
        float w = __expf(stats[sb * 2] - M);
        lt += w * stats[sb * 2 + 1];
        acc += w * part[(((size_t)c * BH_ + bh) * M_ + row) * 64 + d];
    }
    av[((size_t)bh * M_ + row) * 64 + d] = acc / lt;
}

// ======================= fused attn1 -> outh (unchanged) =======================
#define F1_SMEM 178176
__global__ void __launch_bounds__(256) fattn1_kernel(
    const float* __restrict__ qkv, const float* __restrict__ kL,
    const float* __restrict__ Wz, float* __restrict__ outh)
{
    extern __shared__ char sm1[];
    __nv_bfloat16* Qh = (__nv_bfloat16*)sm1;               // [128][72]
    __nv_bfloat16* Ql = Qh + 128 * 72;
    __nv_bfloat16* Kh = (__nv_bfloat16*)(sm1 + 36864);     // [256][72]
    __nv_bfloat16* Kl = Kh + 256 * 72;
    __nv_bfloat16* Wh = (__nv_bfloat16*)(sm1 + 36864 + 73728); // [64][264]
    __nv_bfloat16* Wl = Wh + 64 * 264;

    int tid = threadIdx.x, lane = tid & 31, wid = tid >> 5;
    int bh = blockIdx.x;
    int b = bh >> 3, h = bh & 7;
    int i0base = blockIdx.y << 8;
    int lr = lane & 15, lk = (lane >> 4) << 3;

#pragma unroll
    for (int j = 0; j < 16; ++j) {
        int v = tid + (j << 8);
        int rr = v >> 4, c4 = (v & 15) << 2;
        float4 f = *(const float4*)(kL + (size_t)bh * 16384 + rr * 64 + c4);
        uint2 hi, lo; cvt_split4(f, hi, lo);
        *(uint2*)(Kh + rr * 72 + c4) = hi;
        *(uint2*)(Kl + rr * 72 + c4) = lo;
    }
#pragma unroll
    for (int j = 0; j < 16; ++j) {
        int v = tid + (j << 8);
        int k = v >> 4, n4 = (v & 15) << 2;
        float4 f = *(const float4*)(Wz + (size_t)bh * 16384 + k * 64 + n4);
        float e[4] = {f.x, f.y, f.z, f.w};
#pragma unroll
        for (int q = 0; q < 4; ++q) {
            __nv_bfloat16 hv = __float2bfloat16(e[q]);
            Wh[(n4 + q) * 264 + k] = hv;
            Wl[(n4 + q) * 264 + k] = __float2bfloat16(e[q] - __bfloat162float(hv));
        }
    }

    for (int rblk = 0; rblk < 2; ++rblk) {
        int i0 = i0base + (rblk << 7);
        __syncthreads();
#pragma unroll
        for (int j = 0; j < 8; ++j) {
            int v = tid + (j << 8);
            int rr = v >> 4, c4 = (v & 15) << 2;
            float4 f = *(const float4*)(qkv + (size_t)(b * N_ + i0 + rr) * LDQKV + h * 64 + c4);
            f.x *= 0.125f; f.y *= 0.125f; f.z *= 0.125f; f.w *= 0.125f;
            uint2 hi, lo; cvt_split4(f, hi, lo);
            *(uint2*)(Qh + rr * 72 + c4) = hi;
            *(uint2*)(Ql + rr * 72 + c4) = lo;
        }
        __syncthreads();

        int m0 = wid << 4;
        float Lg[32][4];
#pragma unroll
        for (int j = 0; j < 32; ++j)
#pragma unroll
            for (int q = 0; q < 4; ++q) Lg[j][q] = 0.f;

#pragma unroll
        for (int ksx = 0; ksx < 4; ++ksx) {
            uint32_t qh[4], ql[4];
            ldmx4(qh, smem_u32(Qh + (m0 + lr) * 72 + ksx * 16 + lk));
            ldmx4(ql, smem_u32(Ql + (m0 + lr) * 72 + ksx * 16 + lk));
#pragma unroll
            for (int nb = 0; nb < 16; ++nb) {
                uint32_t th[4], tl[4];
                ldmx4(th, smem_u32(Kh + (nb * 16 + lr) * 72 + ksx * 16 + lk));
                ldmx4(tl, smem_u32(Kl + (nb * 16 + lr) * 72 + ksx * 16 + lk));
                uint32_t b0h[2] = {th[0], th[2]}, b1h[2] = {th[1], th[3]};
                uint32_t b0l[2] = {tl[0], tl[2]}, b1l[2] = {tl[1], tl[3]};
                mma16816(Lg[nb * 2], qh, b0h);
                mma16816(Lg[nb * 2], ql, b0h);
                mma16816(Lg[nb * 2], qh, b0l);
                mma16816(Lg[nb * 2 + 1], qh, b1h);
                mma16816(Lg[nb * 2 + 1], ql, b1h);
                mma16816(Lg[nb * 2 + 1], qh, b1l);
            }
        }

        float mx0 = -1e30f, mx1 = -1e30f;
#pragma unroll
        for (int j = 0; j < 32; ++j) {
            mx0 = fmaxf(mx0, fmaxf(Lg[j][0], Lg[j][1]));
            mx1 = fmaxf(mx1, fmaxf(Lg[j][2], Lg[j][3]));
        }
        mx0 = fmaxf(mx0, __shfl_xor_sync(0xffffffffu, mx0, 1));
        mx0 = fmaxf(mx0, __shfl_xor_sync(0xffffffffu, mx0, 2));
        mx1 = fmaxf(mx1, __shfl_xor_sync(0xffffffffu, mx1, 1));
        mx1 = fmaxf(mx1, __shfl_xor_sync(0xffffffffu, mx1, 2));
        float s0 = 0.f, s1 = 0.f;
#pragma unroll
        for (int j = 0; j < 32; ++j) {
            Lg[j][0] = __expf(Lg[j][0] - mx0);
            Lg[j][1] = __expf(Lg[j][1] - mx0);
            Lg[j][2] = __expf(Lg[j][2] - mx1);
            Lg[j][3] = __expf(Lg[j][3] - mx1);
            s0 += Lg[j][0] + Lg[j][1];
            s1 += Lg[j][2] + Lg[j][3];
        }
        s0 += __shfl_xor_sync(0xffffffffu, s0, 1);
        s0 += __shfl_xor_sync(0xffffffffu, s0, 2);
        s1 += __shfl_xor_sync(0xffffffffu, s1, 1);
        s1 += __shfl_xor_sync(0xffffffffu, s1, 2);
        float inv0 = 1.f / s0, inv1 = 1.f / s1;

        float O[8][4];
#pragma unroll
        for (int j = 0; j < 8; ++j)
#pragma unroll
            for (int q = 0; q < 4; ++q) O[j][q] = 0.f;

#pragma unroll
        for (int t = 0; t < 16; ++t) {
            uint32_t ph[4], pl[4];
            split_pair(Lg[2 * t][0] * inv0,     Lg[2 * t][1] * inv0,     ph[0], pl[0]);
            split_pair(Lg[2 * t][2] * inv1,     Lg[2 * t][3] * inv1,     ph[1], pl[1]);
            split_pair(Lg[2 * t + 1][0] * inv0, Lg[2 * t + 1][1] * inv0, ph[2], pl[2]);
            split_pair(Lg[2 * t + 1][2] * inv1, Lg[2 * t + 1][3] * inv1, ph[3], pl[3]);
#pragma unroll
            for (int nb = 0; nb < 4; ++nb) {
                uint32_t th[4], tl[4];
                ldmx4(th, smem_u32(Wh + (nb * 16 + lr) * 264 + t * 16 + lk));
                ldmx4(tl, smem_u32(Wl + (nb * 16 + lr) * 264 + t * 16 + lk));
                uint32_t b0h[2] = {th[0], th[2]}, b1h[2] = {th[1], th[3]};
                uint32_t b0l[2] = {tl[0], tl[2]}, b1l[2] = {tl[1], tl[3]};
                mma16816(O[nb * 2], ph, b0h);
                mma16816(O[nb * 2], pl, b0h);
                mma16816(O[nb * 2], ph, b0l);
                mma16816(O[nb * 2 + 1], ph, b1h);
                mma16816(O[nb * 2 + 1], pl, b1h);
                mma16816(O[nb * 2 + 1], ph, b1l);
            }
        }

        int rr = lane >> 2, cc = (lane & 3) << 1;
        size_t base = (size_t)bh * N_ + i0 + m0;
#pragma unroll
        for (int nj = 0; nj < 8; ++nj) {
            int col = nj * 8 + cc;
            *(float2*)(outh + (base + rr) * 64 + col) = make_float2(O[nj][0], O[nj][1]);
            *(float2*)(outh + (base + rr + 8) * 64 + col) = make_float2(O[nj][2], O[nj][3]);
        }
    }
}

// ---------------- landmarks ---------------------------------------------------
__global__ void landmarks_kernel(const float* __restrict__ qkv,
                                 float* __restrict__ qL, float* __restrict__ kL)
{
    int bh = blockIdx.x >> 8;
    int lm = blockIdx.x & 255;
    int b = bh >> 3, h = bh & 7;
    int d = threadIdx.x;
    long long base = ((long long)(b * N_ + lm * L_)) * LDQKV + h * D_ + d;
    float sq = 0.f, sk = 0.f;
#pragma unroll 4
    for (int t = 0; t < L_; t++) {
        sq += qkv[base + (long long)t * LDQKV];
        sk += qkv[base + (long long)t * LDQKV + 512];
    }
    long long o = ((long long)bh * M_ + lm) * D_ + d;
    qL[o] = sq * (0.125f / (float)L_);
    kL[o] = sk * (1.0f / (float)L_);
}

// ---------------- softmax (row length 256) — shuffle reduction ----------------
__global__ void softmax256_kernel(float* __restrict__ data)
{
    __shared__ float redm[8], reds[8];
    long long row = blockIdx.x;
    float* p = data + row * 256;
    int t = threadIdx.x, lane = t & 31, w = t >> 5;
    float v = p[t];
    float m = v;
#pragma unroll
    for (int o = 16; o > 0; o >>= 1) m = fmaxf(m, __shfl_xor_sync(0xffffffffu, m, o));
    if (lane == 0) redm[w] = m;
    __syncthreads();
    float M = redm[0];
#pragma unroll
    for (int i = 1; i < 8; ++i) M = fmaxf(M, redm[i]);
    float e = __expf(v - M);
    float s = e;
#pragma unroll
    for (int o = 16; o > 0; o >>= 1) s += __shfl_xor_sync(0xffffffffu, s, o);
    if (lane == 0) reds[w] = s;
    __syncthreads();
    float S = reds[0];
#pragma unroll
    for (int i = 1; i < 8; ++i) S += reds[i];
    p[t] = e * (1.f / S);
}

// ---------------- pinv init ------------------------------------------------------
__global__ void init_bits_kernel(unsigned int* bits)
{
    if (threadIdx.x == 0) { bits[0] = __float_as_uint(1.0f); g_barc = 0u; }
    else bits[1] = 0u;
}

__global__ void colmax_kernel(const float* __restrict__ a, unsigned int* bits)
{
    __shared__ float red[256];
    int bb = blockIdx.x >> 8, j = blockIdx.x & 255;
    int t = threadIdx.x;
    red[t] = fabsf(a[((long long)bb << 16) + ((long long)t << 8) + j]);
    __syncthreads();
    for (int s = 128; s > 0; s >>= 1) { if (t < s) red[t] += red[t + s]; __syncthreads(); }
    if (t == 0) atomicMax(bits + 1, __float_as_uint(red[0]));
}

__global__ void zinit_kernel(const float* __restrict__ a, float* __restrict__ z,
                             const unsigned int* __restrict__ bits)
{
    float denom = __uint_as_float(bits[0]) * __uint_as_float(bits[1]) + 1e-12f;
    float inv = 1.f / denom;
    long long idx = (long long)blockIdx.x * 256 + threadIdx.x;
    long long bb = idx >> 16;
    int r = (int)(idx >> 8) & 255;
    int c = (int)idx & 255;
    z[idx] = a[(bb << 16) + ((long long)c << 8) + r] * inv;
}

// ---------------- depthwise conv residual + head-merge (rolling FIR) -----------
#define CCH 256
__global__ void __launch_bounds__(256) combine_kernel(
    const float* __restrict__ qkv, const float* __restrict__ outh,
    const float* __restrict__ convw, float* __restrict__ pre)
{
    int blk = blockIdx.x;
    int chunk = blk & 31;
    int hhalf = (blk >> 5) & 1;
    int b = blk >> 6;
    int h = hhalf * 4 + (threadIdx.x >> 6);
    int d = threadIdx.x & 63;
    int i0 = chunk * CCH;

    float cw[33];
#pragma unroll
    for (int t = 0; t < 33; ++t) cw[t] = convw[h * 33 + t];

    const float* vcol = qkv + 1024 + h * D_ + d;
    float w[33];
#pragma unroll
    for (int t = 0; t < 33; ++t) {
        int ii = i0 - 16 + t;
        w[t] = (ii >= 0 && ii < N_) ? vcol[(size_t)(b * N_ + ii) * LDQKV] : 0.f;
    }

    const float* orow = outh + (((size_t)(b * H_ + h)) * N_ + i0) * D_ + d;
    float* prow = pre + ((size_t)(b * N_ + i0)) * DIM_ + h * D_ + d;

    for (int i = 0; i < CCH; ++i) {
        float s = 0.f;
#pragma unroll
        for (int t = 0; t < 33; ++t) s += cw[t] * w[t];
        prow[(size_t)i * DIM_] = orow[(size_t)i * D_] + s;
#pragma unroll
        for (int t = 0; t < 32; ++t) w[t] = w[t + 1];
        int ii = i0 + i + 17;
        w[32] = (ii >= 0 && ii < N_) ? vcol[(size_t)(b * N_ + ii) * LDQKV] : 0.f;
    }
}

// ---------------- host side -----------------------------------------------------
struct GArgs {
    const float *A, *B; float* C; const float* bias;
    int lda, ldb, ldc;
    long long aO, aI, bO, bI, cO, cI;
    int transB, bmode; float alphaB, scale;
    int kchunks, klen; long long csplit;
};

template<int BN, int NTRM>
static inline void launch_bgemm(int M, int N, int batches, const GArgs& g, cudaStream_t st)
{
    constexpr int TERMS = (NTRM == 3) ? 2 : 1;
    const size_t smem = 2ull * TERMS * (128 + BN) * SPAD * sizeof(__nv_bfloat16);
    static bool attr_set = false;
    if (!attr_set) {
        cudaFuncSetAttribute(bgemm_kernel<BN, NTRM>,
                             cudaFuncAttributeMaxDynamicSharedMemorySize, (int)smem);
        attr_set = true;
    }
    dim3 grid(N / BN, (M / 128) * g.kchunks, batches);
    bgemm_kernel<BN, NTRM><<<grid, 256, smem, st>>>(
        g.A, g.B, g.C, g.bias, g.lda, g.ldb, g.ldc,
        g.aO, g.aI, g.bO, g.bI, g.cO, g.cI,
        g.transB, g.bmode, g.alphaB, g.scale,
        g.kchunks, g.klen, g.csplit);
}

extern "C" void kernel_launch(void* const* d_in, const int* in_sizes, int n_in,
                              void* d_out, int out_size)
{
    const float* x     = (const float*)d_in[0];
    const float* Wqkv  = (const float*)d_in[1];
    const float* Wout  = (const float*)d_in[2];
    const float* bout  = (const float*)d_in[3];
    const float* convw = (const float*)d_in[4];
    float* out = (float*)d_out;

    float *qkv, *qL, *kL, *attn2, *z0, *z1, *xz, *t2, *t3, *av, *W, *outh, *pre;
    float *avpart, *avstats;
    unsigned int* bits;
    cudaGetSymbolAddress((void**)&qkv,    g_qkv);
    cudaGetSymbolAddress((void**)&qL,     g_qL);
    cudaGetSymbolAddress((void**)&kL,     g_kL);
    cudaGetSymbolAddress((void**)&attn2,  g_attn2);
    cudaGetSymbolAddress((void**)&z0,     g_z0);
    cudaGetSymbolAddress((void**)&z1,     g_z1);
    cudaGetSymbolAddress((void**)&xz,     g_xz);
    cudaGetSymbolAddress((void**)&t2,     g_t2);
    cudaGetSymbolAddress((void**)&t3,     g_t3);
    cudaGetSymbolAddress((void**)&av,     g_av);
    cudaGetSymbolAddress((void**)&W,      g_W);
    cudaGetSymbolAddress((void**)&outh,   g_outh);
    cudaGetSymbolAddress((void**)&pre,    g_pre);
    cudaGetSymbolAddress((void**)&avpart, g_avpart);
    cudaGetSymbolAddress((void**)&avstats,g_avstats);
    cudaGetSymbolAddress((void**)&bits,   g_bits);

    cudaFuncSetAttribute(fattn3_kernel, cudaFuncAttributeMaxDynamicSharedMemorySize, F3_SMEM);
    cudaFuncSetAttribute(fattn1_kernel, cudaFuncAttributeMaxDynamicSharedMemorySize, F1_SMEM);

    static cudaStream_t s1 = nullptr;
    static cudaEvent_t ev_land = nullptr, ev_z = nullptr;
    if (!s1) {
        cudaStreamCreateWithFlags(&s1, cudaStreamNonBlocking);
        cudaEventCreateWithFlags(&ev_land, cudaEventDisableTiming);
        cudaEventCreateWithFlags(&ev_z, cudaEventDisableTiming);
    }
    cudaStream_t s0 = 0;

    const long long MM = (long long)M_ * M_;
    const long long MD = (long long)M_ * D_;

    // 1) qkv = x @ Wqkv            [s0]
    { GArgs g{x, Wqkv, qkv, nullptr, 512, 1536, LDQKV,
              0,0, 0,0, 0,0, 0, 0, 0.f, 1.f, 1, 512, 0};
      launch_bgemm<128, 3>(NT_, 1536, 1, g, s0); }

    // 2) landmarks                 [s0]
    landmarks_kernel<<<BH_ * M_, 64, 0, s0>>>(qkv, qL, kL);
    cudaEventRecord(ev_land, s0);

    // ---- fork: pinv branch on s1 ----
    cudaStreamWaitEvent(s1, ev_land, 0);

    // attn2 logits + softmax
    { GArgs g{qL, kL, attn2, nullptr, 64, 64, M_,
              8*MD, MD, 8*MD, MD, 8*MM, MM, 1, 0, 0.f, 1.f, 1, 64, 0};
      launch_bgemm<64, 3>(M_, M_, BH_, g, s1); }
    softmax256_kernel<<<BH_ * M_, 256, 0, s1>>>(attn2);

    // pinv init (also resets grid barrier counter)
    init_bits_kernel<<<1, 2, 0, s1>>>(bits);
    colmax_kernel<<<BH_ * M_, 256, 0, s1>>>(attn2, bits);
    zinit_kernel<<<BH_ * M_, 256, 0, s1>>>(attn2, z0, bits);

    // fused 6-iteration Newton-Schulz (one persistent kernel, grid barriers)
    pinv_kernel<<<256, 256, 0, s1>>>(attn2, z0, z1, xz, t2, t3);
    cudaEventRecord(ev_z, s1);

    // ---- meanwhile on s0: fused attn3 -> av ----
    { dim3 grid(BH_, 8);
      fattn3_kernel<<<grid, 256, F3_SMEM, s0>>>(qkv, qL, avpart, avstats); }
    avreduce2_kernel<<<BH_ * M_, 64, 0, s0>>>(avpart, avstats, av);

    // ---- join ----
    cudaStreamWaitEvent(s0, ev_z, 0);

    // W = z @ av
    { GArgs g{z0, av, W, nullptr, M_, D_, D_,
              8*MM, MM, 8*MD, MD, 8*MD, MD, 0, 0, 0.f, 1.f, 1, M_, 0};
      launch_bgemm<64, 3>(M_, D_, BH_, g, s0); }

    // fused attn1 -> outh (256 rows per CTA)
    { dim3 grid(BH_, N_ / 256);
      fattn1_kernel<<<grid, 256, F1_SMEM, s0>>>(qkv, kL, W, outh); }

    // depthwise conv residual + merge heads (rolling FIR)
    combine_kernel<<<B_ * 2 * (N_ / CCH), 256, 0, s0>>>(qkv, outh, convw, pre);

    // out = pre @ Wout + bout
    { GArgs g{pre, Wout, out, bout, DIM_, DIM_, DIM_,
              0,0, 0,0, 0,0, 0, 0, 0.f, 1.f, 1, DIM_, 0};
      launch_bgemm<128, 3>(NT_, DIM_, 1, g, s0); }
}

// round 17
// speedup vs baseline: 1.4912x; 1.4810x over previous
#include <cuda_runtime.h>
#include <cuda_bf16.h>
#include <cstdint>

// ----------------------------------------------------------------------------
// NystromAttention: b=4, n=8192, dim=512, h=8, d=64, m=256, l=32, pinv=6, K=33
// R17: conv residual computed early into pre (3rd stream); fattn1 adds into
//      pre directly (combine+outh eliminated); Wqkv/Wout pre-split to bf16
//      hi/lo once (BF16B path in bgemm removes redundant B conversions).
// ----------------------------------------------------------------------------

#define B_   4
#define N_   8192
#define DIM_ 512
#define H_   8
#define D_   64
#define M_   256
#define L_   32
#define LDQKV 1536
#define NT_  (B_*N_)      // 32768
#define BH_  (B_*H_)      // 32

// ---------------- scratch (static device globals; no allocation) -------------
__device__ float g_qkv[(long long)NT_ * LDQKV];
__device__ float g_qL[BH_ * M_ * D_];
__device__ float g_kL[BH_ * M_ * D_];
__device__ float g_attn2[BH_ * M_ * M_];
__device__ float g_z0[BH_ * M_ * M_];
__device__ float g_z1[BH_ * M_ * M_];
__device__ float g_xz[BH_ * M_ * M_];
__device__ float g_t2[BH_ * M_ * M_];
__device__ float g_t3[BH_ * M_ * M_];
__device__ float g_av[BH_ * M_ * D_];
__device__ float g_W[BH_ * M_ * D_];
__device__ float g_pre[(long long)NT_ * DIM_];
__device__ float g_avpart[8 * BH_ * M_ * D_];
__device__ float g_avstats[8 * BH_ * M_ * 2];
__device__ __nv_bfloat16 g_wqh[1536 * 512];
__device__ __nv_bfloat16 g_wql[1536 * 512];
__device__ __nv_bfloat16 g_woh[512 * 512];
__device__ __nv_bfloat16 g_wol[512 * 512];
__device__ unsigned int g_bits[2];
__device__ unsigned int g_barc;

// ======================= mma.sync helpers =====================================
__device__ __forceinline__ uint32_t smem_u32(const void* p) {
    uint32_t a;
    asm("{ .reg .u64 tmp; cvta.to.shared.u64 tmp, %1; cvt.u32.u64 %0, tmp; }"
        : "=r"(a) : "l"(p));
    return a;
}
__device__ __forceinline__ void ldmx4(uint32_t* d, uint32_t addr) {
    asm volatile("ldmatrix.sync.aligned.m8n8.x4.shared.b16 {%0,%1,%2,%3}, [%4];"
                 : "=r"(d[0]), "=r"(d[1]), "=r"(d[2]), "=r"(d[3]) : "r"(addr));
}
__device__ __forceinline__ void mma16816(float* c, const uint32_t* a, const uint32_t* b) {
    asm volatile("mma.sync.aligned.m16n8k16.row.col.f32.bf16.bf16.f32 "
                 "{%0,%1,%2,%3}, {%4,%5,%6,%7}, {%8,%9}, {%0,%1,%2,%3};"
                 : "+f"(c[0]), "+f"(c[1]), "+f"(c[2]), "+f"(c[3])
                 : "r"(a[0]), "r"(a[1]), "r"(a[2]), "r"(a[3]), "r"(b[0]), "r"(b[1]));
}
__device__ __forceinline__ uint32_t pack2(__nv_bfloat16 a, __nv_bfloat16 b) {
    __nv_bfloat162 t; t.x = a; t.y = b;
    return *(uint32_t*)&t;
}
__device__ __forceinline__ void cvt_split4(float4 f, uint2& hi, uint2& lo) {
    __nv_bfloat16 h0 = __float2bfloat16(f.x), h1 = __float2bfloat16(f.y);
    __nv_bfloat16 h2 = __float2bfloat16(f.z), h3 = __float2bfloat16(f.w);
    __nv_bfloat16 l0 = __float2bfloat16(f.x - __bfloat162float(h0));
    __nv_bfloat16 l1 = __float2bfloat16(f.y - __bfloat162float(h1));
    __nv_bfloat16 l2 = __float2bfloat16(f.z - __bfloat162float(h2));
    __nv_bfloat16 l3 = __float2bfloat16(f.w - __bfloat162float(h3));
    hi.x = pack2(h0, h1); hi.y = pack2(h2, h3);
    lo.x = pack2(l0, l1); lo.y = pack2(l2, l3);
}
__device__ __forceinline__ uint2 cvt_hi4(float4 f) {
    uint2 hi;
    hi.x = pack2(__float2bfloat16(f.x), __float2bfloat16(f.y));
    hi.y = pack2(__float2bfloat16(f.z), __float2bfloat16(f.w));
    return hi;
}
__device__ __forceinline__ void split_pair(float a, float b, uint32_t& hi, uint32_t& lo) {
    __nv_bfloat16 ha = __float2bfloat16(a), hb = __float2bfloat16(b);
    hi = pack2(ha, hb);
    lo = pack2(__float2bfloat16(a - __bfloat162float(ha)),
               __float2bfloat16(b - __bfloat162float(hb)));
}

#define SPAD 40

// ======================= unified batched bf16-split GEMM ======================
// BF16B=1: B supplied pre-split as bf16 hi/lo in [N,K] row-major (no transB/bmode).
template<int BN, int NTRM, int BF16B>
__global__ void __launch_bounds__(256) bgemm_kernel(
    const float* __restrict__ A, const float* __restrict__ B,
    const __nv_bfloat16* __restrict__ B16h, const __nv_bfloat16* __restrict__ B16l,
    float* __restrict__ C, const float* __restrict__ bias,
    int lda, int ldb, int ldc,
    long long aOut, long long aIn, long long bOut, long long bIn,
    long long cOut, long long cIn,
    int transB, int bmode, float alphaB, float scale,
    int kchunks, int kchunk_len, long long csplit)
{
    extern __shared__ __nv_bfloat16 db[];
    constexpr int TERMS = (NTRM == 3) ? 2 : 1;
    constexpr int ASZ = 128 * SPAD;
    constexpr int BSZ = BN * SPAD;
    constexpr int STG = TERMS * (ASZ + BSZ);

    constexpr int WN = BN / 2;
    constexpr int JN = WN / 8;
    constexpr int BJ = BN / 32;

    int tid = threadIdx.x, lane = tid & 31, wid = tid >> 5;
    int bb = blockIdx.z, ob = bb >> 3, ib = bb & 7;
    int ks = blockIdx.y % kchunks;
    int mtile = blockIdx.y / kchunks;
    int row0 = mtile << 7;
    int col0 = blockIdx.x * BN;

    const float* Ab = A + (long long)ob * aOut + (long long)ib * aIn;
    const float* Bb = B ? B + (long long)ob * bOut + (long long)ib * bIn : nullptr;
    float*       Cb = C + (long long)ob * cOut + (long long)ib * cIn + (long long)ks * csplit;

    int k_begin = ks * kchunk_len;
    int NC = kchunk_len >> 5;

    int wm = (wid >> 1) << 5;
    int wn = (wid & 1) * WN;

    float acc[2][JN][4];
#pragma unroll
    for (int i = 0; i < 2; ++i)
#pragma unroll
        for (int j = 0; j < JN; ++j)
#pragma unroll
            for (int q = 0; q < 4; ++q) acc[i][j][q] = 0.f;

    int lr = lane & 15, lk = (lane >> 4) << 3;

    int a_r = tid >> 3, a_kq = (tid & 7) << 2;
    int bt_r = tid >> 3, bt_kq = (tid & 7) << 2;
    int bn_kk = tid / (BN / 4), bn_nq = (tid % (BN / 4)) << 2;

    float4 aReg[4], bReg[BF16B ? 1 : BJ];
    uint2 bhReg[BF16B ? BJ : 1], blReg[BF16B ? BJ : 1];

    auto ldg_tile = [&](int k0) {
#pragma unroll
        for (int j = 0; j < 4; ++j)
            aReg[j] = *(const float4*)(Ab + (long long)(row0 + a_r + j * 32) * lda + k0 + a_kq);
        if (BF16B) {
#pragma unroll
            for (int j = 0; j < BJ; ++j) {
                size_t o = (size_t)(col0 + bt_r + j * 32) * ldb + k0 + bt_kq;
                bhReg[j] = *(const uint2*)(B16h + o);
                blReg[j] = *(const uint2*)(B16l + o);
            }
        } else if (transB) {
#pragma unroll
            for (int j = 0; j < BJ; ++j)
                bReg[j] = *(const float4*)(Bb + (long long)(col0 + bt_r + j * 32) * ldb + k0 + bt_kq);
        } else {
#pragma unroll
            for (int j = 0; j < BJ; ++j)
                bReg[j] = *(const float4*)(Bb + (long long)(k0 + bn_kk + j * (256 / (BN / 4))) * ldb + col0 + bn_nq);
        }
    };

    auto sts_tile = [&](int s, int k0tile) {
        __nv_bfloat16* As0 = db + s * STG;
        __nv_bfloat16* As1 = As0 + ASZ;
        __nv_bfloat16* Bs0 = db + s * STG + TERMS * ASZ;
        __nv_bfloat16* Bs1 = Bs0 + BSZ;
#pragma unroll
        for (int j = 0; j < 4; ++j) {
            int r = a_r + j * 32;
            if (NTRM == 3) {
                uint2 hi, lo; cvt_split4(aReg[j], hi, lo);
                *(uint2*)&As0[r * SPAD + a_kq] = hi;
                *(uint2*)&As1[r * SPAD + a_kq] = lo;
            } else {
                *(uint2*)&As0[r * SPAD + a_kq] = cvt_hi4(aReg[j]);
            }
        }
        if (BF16B) {
#pragma unroll
            for (int j = 0; j < BJ; ++j) {
                int r = bt_r + j * 32;
                *(uint2*)&Bs0[r * SPAD + bt_kq] = bhReg[j];
                if (NTRM == 3) *(uint2*)&Bs1[r * SPAD + bt_kq] = blReg[j];
            }
        } else if (transB) {
#pragma unroll
            for (int j = 0; j < BJ; ++j) {
                int r = bt_r + j * 32;
                if (NTRM == 3) {
                    uint2 hi, lo; cvt_split4(bReg[j], hi, lo);
                    *(uint2*)&Bs0[r * SPAD + bt_kq] = hi;
                    *(uint2*)&Bs1[r * SPAD + bt_kq] = lo;
                } else {
                    *(uint2*)&Bs0[r * SPAD + bt_kq] = cvt_hi4(bReg[j]);
                }
            }
        } else {
#pragma unroll
            for (int j = 0; j < BJ; ++j) {
                int kk = bn_kk + j * (256 / (BN / 4));
                float4 f = bReg[j];
                if (bmode) {
                    int gk = k0tile + kk, gn = col0 + bn_nq;
                    f.x = ((gk == gn + 0) ? alphaB : 0.f) - f.x;
                    f.y = ((gk == gn + 1) ? alphaB : 0.f) - f.y;
                    f.z = ((gk == gn + 2) ? alphaB : 0.f) - f.z;
                    f.w = ((gk == gn + 3) ? alphaB : 0.f) - f.w;
                }
                float e[4] = {f.x, f.y, f.z, f.w};
#pragma unroll
                for (int q = 0; q < 4; ++q) {
                    __nv_bfloat16 h = __float2bfloat16(e[q]);
                    Bs0[(bn_nq + q) * SPAD + kk] = h;
                    if (NTRM == 3)
                        Bs1[(bn_nq + q) * SPAD + kk] = __float2bfloat16(e[q] - __bfloat162float(h));
                }
            }
        }
    };

    auto compute_tile = [&](int s) {
        __nv_bfloat16* As0 = db + s * STG;
        __nv_bfloat16* As1 = As0 + ASZ;
        __nv_bfloat16* Bs0 = db + s * STG + TERMS * ASZ;
        __nv_bfloat16* Bs1 = Bs0 + BSZ;
#pragma unroll
        for (int kss = 0; kss < 32; kss += 16) {
            uint32_t ahi[2][4], alo[2][4], bhi[JN][2], blo[JN][2];
#pragma unroll
            for (int im = 0; im < 2; ++im) {
                ldmx4(ahi[im], smem_u32(&As0[(wm + (im << 4) + lr) * SPAD + kss + lk]));
                if (NTRM == 3)
                    ldmx4(alo[im], smem_u32(&As1[(wm + (im << 4) + lr) * SPAD + kss + lk]));
            }
#pragma unroll
            for (int jb = 0; jb < JN / 2; ++jb) {
                uint32_t t[4];
                ldmx4(t, smem_u32(&Bs0[(wn + (jb << 4) + lr) * SPAD + kss + lk]));
                bhi[jb * 2][0] = t[0]; bhi[jb * 2 + 1][0] = t[1];
                bhi[jb * 2][1] = t[2]; bhi[jb * 2 + 1][1] = t[3];
                if (NTRM == 3) {
                    ldmx4(t, smem_u32(&Bs1[(wn + (jb << 4) + lr) * SPAD + kss + lk]));
                    blo[jb * 2][0] = t[0]; blo[jb * 2 + 1][0] = t[1];
                    blo[jb * 2][1] = t[2]; blo[jb * 2 + 1][1] = t[3];
                }
            }
#pragma unroll
            for (int im = 0; im < 2; ++im)
#pragma unroll
                for (int jn = 0; jn < JN; ++jn) {
                    mma16816(acc[im][jn], ahi[im], bhi[jn]);
                    if (NTRM == 3) {
                        mma16816(acc[im][jn], alo[im], bhi[jn]);
                        mma16816(acc[im][jn], ahi[im], blo[jn]);
                    }
                }
        }
    };

    ldg_tile(k_begin);
    sts_tile(0, k_begin);
    __syncthreads();

    for (int c = 0; c < NC; ++c) {
        int kn = k_begin + ((c + 1) << 5);
        if (c + 1 < NC) ldg_tile(kn);
        compute_tile(c & 1);
        if (c + 1 < NC) {
            sts_tile((c + 1) & 1, kn);
            __syncthreads();
        }
    }

    int rr = lane >> 2, cc = (lane & 3) << 1;
#pragma unroll
    for (int im = 0; im < 2; ++im) {
        int grow = row0 + wm + (im << 4) + rr;
#pragma unroll
        for (int jn = 0; jn < JN; ++jn) {
            int gcol = col0 + wn + (jn << 3) + cc;
            float b0 = 0.f, b1 = 0.f;
            if (bias) { b0 = bias[gcol]; b1 = bias[gcol + 1]; }
            float2 v0 = make_float2(scale * acc[im][jn][0] + b0, scale * acc[im][jn][1] + b1);
            float2 v1 = make_float2(scale * acc[im][jn][2] + b0, scale * acc[im][jn][3] + b1);
            *(float2*)(Cb + (long long)grow * ldc + gcol) = v0;
            *(float2*)(Cb + (long long)(grow + 8) * ldc + gcol) = v1;
        }
    }
}

// weight transpose+split: out[j*K+k] = split(w[k*N+j])
__global__ void wsplit_kernel(const float* __restrict__ w,
                              __nv_bfloat16* __restrict__ hi,
                              __nv_bfloat16* __restrict__ lo, int K, int N)
{
    long long idx = (long long)blockIdx.x * 256 + threadIdx.x;
    if (idx >= (long long)K * N) return;
    int j = (int)(idx / K), k = (int)(idx % K);
    float a = w[(size_t)k * N + j];
    __nv_bfloat16 h = __float2bfloat16(a);
    hi[idx] = h;
    lo[idx] = __float2bfloat16(a - __bfloat162float(h));
}

// ======================= persistent fused Newton-Schulz (unchanged) ===========
__device__ __forceinline__ void gridbar(unsigned int target) {
    __threadfence();
    __syncthreads();
    if (threadIdx.x == 0) {
        atomicAdd(&g_barc, 1u);
        while (atomicAdd(&g_barc, 0u) < target) __nanosleep(64);
    }
    __syncthreads();
    __threadfence();
}

template<int NTRM>
__device__ __forceinline__ void gemm256_job(
    const float* __restrict__ Ab, const float* __restrict__ Bb, float* __restrict__ Cb,
    int row0, int col0, int bmode, float alphaB, float scale,
    __nv_bfloat16* As0, __nv_bfloat16* As1,
    __nv_bfloat16* Bs0, __nv_bfloat16* Bs1)
{
    int tid = threadIdx.x, lane = tid & 31, wid = tid >> 5;
    int wm = (wid >> 1) << 5;
    int wn = (wid & 1) << 5;
    int lr = lane & 15, lk = (lane >> 4) << 3;

    float acc[2][4][4];
#pragma unroll
    for (int i = 0; i < 2; ++i)
#pragma unroll
        for (int j = 0; j < 4; ++j)
#pragma unroll
            for (int q = 0; q < 4; ++q) acc[i][j][q] = 0.f;

    int a_r = tid >> 3, a_kq = (tid & 7) << 2;
    int bn_kk = tid >> 4, bn_nq = (tid & 15) << 2;

    float4 aReg[4], bReg[2];
#pragma unroll
    for (int j = 0; j < 4; ++j)
        aReg[j] = *(const float4*)(Ab + (size_t)(row0 + a_r + j * 32) * 256 + a_kq);
#pragma unroll
    for (int j = 0; j < 2; ++j)
        bReg[j] = *(const float4*)(Bb + (size_t)(bn_kk + j * 16) * 256 + col0 + bn_nq);

    for (int k0 = 0; k0 < 256; k0 += 32) {
        __syncthreads();
#pragma unroll
        for (int j = 0; j < 4; ++j) {
            int r = a_r + j * 32;
            if (NTRM == 3) {
                uint2 hi, lo; cvt_split4(aReg[j], hi, lo);
                *(uint2*)&As0[r * SPAD + a_kq] = hi;
                *(uint2*)&As1[r * SPAD + a_kq] = lo;
            } else {
                *(uint2*)&As0[r * SPAD + a_kq] = cvt_hi4(aReg[j]);
            }
        }
#pragma unroll
        for (int j = 0; j < 2; ++j) {
            int kk = bn_kk + j * 16;
            float4 f = bReg[j];
            if (bmode) {
                int gk = k0 + kk, gn = col0 + bn_nq;
                f.x = ((gk == gn + 0) ? alphaB : 0.f) - f.x;
                f.y = ((gk == gn + 1) ? alphaB : 0.f) - f.y;
                f.z = ((gk == gn + 2) ? alphaB : 0.f) - f.z;
                f.w = ((gk == gn + 3) ? alphaB : 0.f) - f.w;
            }
            float e[4] = {f.x, f.y, f.z, f.w};
#pragma unroll
            for (int q = 0; q < 4; ++q) {
                __nv_bfloat16 h = __float2bfloat16(e[q]);
                Bs0[(bn_nq + q) * SPAD + kk] = h;
                if (NTRM == 3)
                    Bs1[(bn_nq + q) * SPAD + kk] = __float2bfloat16(e[q] - __bfloat162float(h));
            }
        }
        __syncthreads();

        int kn = k0 + 32;
        if (kn < 256) {
#pragma unroll
            for (int j = 0; j < 4; ++j)
                aReg[j] = *(const float4*)(Ab + (size_t)(row0 + a_r + j * 32) * 256 + kn + a_kq);
#pragma unroll
            for (int j = 0; j < 2; ++j)
                bReg[j] = *(const float4*)(Bb + (size_t)(kn + bn_kk + j * 16) * 256 + col0 + bn_nq);
        }

#pragma unroll
        for (int kss = 0; kss < 32; kss += 16) {
            uint32_t ahi[2][4], alo[2][4], bhi[4][2], blo[4][2];
#pragma unroll
            for (int im = 0; im < 2; ++im) {
                ldmx4(ahi[im], smem_u32(&As0[(wm + (im << 4) + lr) * SPAD + kss + lk]));
                if (NTRM == 3)
                    ldmx4(alo[im], smem_u32(&As1[(wm + (im << 4) + lr) * SPAD + kss + lk]));
            }
#pragma unroll
            for (int jb = 0; jb < 2; ++jb) {
                uint32_t t[4];
                ldmx4(t, smem_u32(&Bs0[(wn + (jb << 4) + lr) * SPAD + kss + lk]));
                bhi[jb * 2][0] = t[0]; bhi[jb * 2 + 1][0] = t[1];
                bhi[jb * 2][1] = t[2]; bhi[jb * 2 + 1][1] = t[3];
                if (NTRM == 3) {
                    ldmx4(t, smem_u32(&Bs1[(wn + (jb << 4) + lr) * SPAD + kss + lk]));
                    blo[jb * 2][0] = t[0]; blo[jb * 2 + 1][0] = t[1];
                    blo[jb * 2][1] = t[2]; blo[jb * 2 + 1][1] = t[3];
                }
            }
#pragma unroll
            for (int im = 0; im < 2; ++im)
#pragma unroll
                for (int jn = 0; jn < 4; ++jn) {
                    mma16816(acc[im][jn], ahi[im], bhi[jn]);
                    if (NTRM == 3) {
                        mma16816(acc[im][jn], alo[im], bhi[jn]);
                        mma16816(acc[im][jn], ahi[im], blo[jn]);
                    }
                }
        }
    }

    int rr = lane >> 2, cc = (lane & 3) << 1;
#pragma unroll
    for (int im = 0; im < 2; ++im) {
        int grow = row0 + wm + (im << 4) + rr;
#pragma unroll
        for (int jn = 0; jn < 4; ++jn) {
            int gcol = col0 + wn + (jn << 3) + cc;
            *(float2*)(Cb + (size_t)grow * 256 + gcol) =
                make_float2(scale * acc[im][jn][0], scale * acc[im][jn][1]);
            *(float2*)(Cb + (size_t)(grow + 8) * 256 + gcol) =
                make_float2(scale * acc[im][jn][2], scale * acc[im][jn][3]);
        }
    }
}

__global__ void __launch_bounds__(256) pinv_kernel(
    const float* __restrict__ attn2, float* __restrict__ z0, float* __restrict__ z1,
    float* __restrict__ xz, float* __restrict__ t2, float* __restrict__ t3)
{
    __shared__ __nv_bfloat16 As0[128 * SPAD], As1[128 * SPAD];
    __shared__ __nv_bfloat16 Bs0[64 * SPAD],  Bs1[64 * SPAD];

    int cta = blockIdx.x;
    int bb = cta >> 3;
    int mtile = (cta >> 2) & 1;
    int ntile = cta & 3;
    int row0 = mtile << 7, col0 = ntile << 6;
    size_t off = (size_t)bb << 16;

    unsigned int step = 0;
    for (int it = 0; it < 6; ++it) {
        const float* zi = (it & 1) ? z1 : z0;
        float* zo = (it & 1) ? z0 : z1;
        if (it < 5) {
            gemm256_job<1>(attn2 + off, zi + off, xz + off, row0, col0, 0, 0.f, 1.f, As0, As1, Bs0, Bs1);
            gridbar(++step * 256u);
            gemm256_job<1>(xz + off, xz + off, t2 + off, row0, col0, 1, 7.f, 1.f, As0, As1, Bs0, Bs1);
            gridbar(++step * 256u);
            gemm256_job<1>(xz + off, t2 + off, t3 + off, row0, col0, 1, 15.f, 1.f, As0, As1, Bs0, Bs1);
            gridbar(++step * 256u);
            gemm256_job<1>(zi + off, t3 + off, zo + off, row0, col0, 1, 13.f, 0.25f, As0, As1, Bs0, Bs1);
            gridbar(++step * 256u);
        } else {
            gemm256_job<3>(attn2 + off, zi + off, xz + off, row0, col0, 0, 0.f, 1.f, As0, As1, Bs0, Bs1);
            gridbar(++step * 256u);
            gemm256_job<3>(xz + off, xz + off, t2 + off, row0, col0, 1, 7.f, 1.f, As0, As1, Bs0, Bs1);
            gridbar(++step * 256u);
            gemm256_job<3>(xz + off, t2 + off, t3 + off, row0, col0, 1, 15.f, 1.f, As0, As1, Bs0, Bs1);
            gridbar(++step * 256u);
            gemm256_job<3>(zi + off, t3 + off, zo + off, row0, col0, 1, 13.f, 0.25f, As0, As1, Bs0, Bs1);
        }
    }
}

// ======================= fused attn3 -> av (flash, split over keys) ===========
#define F3_SMEM 110592
__global__ void __launch_bounds__(256) fattn3_kernel(
    const float* __restrict__ qkv, const float* __restrict__ qL,
    float* __restrict__ part, float* __restrict__ stats)
{
    extern __shared__ char sm3[];
    __nv_bfloat16* Qh = (__nv_bfloat16*)sm3;              // [256][72]
    __nv_bfloat16* Ql = Qh + 256 * 72;
    __nv_bfloat16* Kh = (__nv_bfloat16*)(sm3 + 73728);    // [64][72]
    __nv_bfloat16* Kl = Kh + 64 * 72;
    __nv_bfloat16* Vh = (__nv_bfloat16*)(sm3 + 73728 + 18432); // [64 d][72 key]
    __nv_bfloat16* Vl = Vh + 64 * 72;

    int tid = threadIdx.x, lane = tid & 31, wid = tid >> 5;
    int bh = blockIdx.x, kc = blockIdx.y;
    int b = bh >> 3, h = bh & 7;
    int lr = lane & 15, lk = (lane >> 4) << 3;
    int m0 = wid << 5;

#pragma unroll
    for (int j = 0; j < 16; ++j) {
        int v = tid + (j << 8);
        int rr = v >> 4, c4 = (v & 15) << 2;
        float4 f = *(const float4*)(qL + (size_t)bh * 16384 + rr * 64 + c4);
        uint2 hi, lo; cvt_split4(f, hi, lo);
        *(uint2*)(Qh + rr * 72 + c4) = hi;
        *(uint2*)(Ql + rr * 72 + c4) = lo;
    }

    float O[2][8][4];
    float mst[2][2], lst[2][2];
#pragma unroll
    for (int mt = 0; mt < 2; ++mt) {
        mst[mt][0] = mst[mt][1] = -1e30f;
        lst[mt][0] = lst[mt][1] = 0.f;
#pragma unroll
        for (int j = 0; j < 8; ++j)
#pragma unroll
            for (int q = 0; q < 4; ++q) O[mt][j][q] = 0.f;
    }

    int s_rr = tid >> 4, s_c4 = (tid & 15) << 2;
    float4 kReg[4], vReg[4];
    {
        int key0 = kc << 10;
#pragma unroll
        for (int j = 0; j < 4; ++j) {
            int rr = s_rr + j * 16;
            kReg[j] = *(const float4*)(qkv + (size_t)(b * N_ + key0 + rr) * LDQKV + 512 + h * 64 + s_c4);
            vReg[j] = *(const float4*)(qkv + (size_t)(b * N_ + key0 + rr) * LDQKV + 1024 + h * 64 + s_c4);
        }
    }

    for (int c = 0; c < 16; ++c) {
        __syncthreads();
#pragma unroll
        for (int j = 0; j < 4; ++j) {
            int rr = s_rr + j * 16;
            uint2 hi, lo; cvt_split4(kReg[j], hi, lo);
            *(uint2*)(Kh + rr * 72 + s_c4) = hi;
            *(uint2*)(Kl + rr * 72 + s_c4) = lo;
            float e[4] = {vReg[j].x, vReg[j].y, vReg[j].z, vReg[j].w};
#pragma unroll
            for (int q = 0; q < 4; ++q) {
                __nv_bfloat16 hv = __float2bfloat16(e[q]);
                Vh[(s_c4 + q) * 72 + rr] = hv;
                Vl[(s_c4 + q) * 72 + rr] = __float2bfloat16(e[q] - __bfloat162float(hv));
            }
        }
        __syncthreads();

        if (c + 1 < 16) {
            int key0 = (kc << 10) + ((c + 1) << 6);
#pragma unroll
            for (int j = 0; j < 4; ++j) {
                int rr = s_rr + j * 16;
                kReg[j] = *(const float4*)(qkv + (size_t)(b * N_ + key0 + rr) * LDQKV + 512 + h * 64 + s_c4);
                vReg[j] = *(const float4*)(qkv + (size_t)(b * N_ + key0 + rr) * LDQKV + 1024 + h * 64 + s_c4);
            }
        }

#pragma unroll
        for (int mt = 0; mt < 2; ++mt) {
            float Lg[8][4];
#pragma unroll
            for (int j = 0; j < 8; ++j)
#pragma unroll
                for (int q = 0; q < 4; ++q) Lg[j][q] = 0.f;
#pragma unroll
            for (int ksx = 0; ksx < 4; ++ksx) {
                uint32_t qh[4], ql[4];
                ldmx4(qh, smem_u32(Qh + (m0 + mt * 16 + lr) * 72 + ksx * 16 + lk));
                ldmx4(ql, smem_u32(Ql + (m0 + mt * 16 + lr) * 72 + ksx * 16 + lk));
#pragma unroll
                for (int nb = 0; nb < 4; ++nb) {
                    uint32_t th[4], tl[4];
                    ldmx4(th, smem_u32(Kh + (nb * 16 + lr) * 72 + ksx * 16 + lk));
                    ldmx4(tl, smem_u32(Kl + (nb * 16 + lr) * 72 + ksx * 16 + lk));
                    uint32_t b0h[2] = {th[0], th[2]}, b1h[2] = {th[1], th[3]};
                    uint32_t b0l[2] = {tl[0], tl[2]}, b1l[2] = {tl[1], tl[3]};
                    mma16816(Lg[nb * 2], qh, b0h);
                    mma16816(Lg[nb * 2], ql, b0h);
                    mma16816(Lg[nb * 2], qh, b0l);
                    mma16816(Lg[nb * 2 + 1], qh, b1h);
                    mma16816(Lg[nb * 2 + 1], ql, b1h);
                    mma16816(Lg[nb * 2 + 1], qh, b1l);
                }
            }
            float cm0 = -1e30f, cm1 = -1e30f;
#pragma unroll
            for (int j = 0; j < 8; ++j) {
                cm0 = fmaxf(cm0, fmaxf(Lg[j][0], Lg[j][1]));
                cm1 = fmaxf(cm1, fmaxf(Lg[j][2], Lg[j][3]));
            }
            cm0 = fmaxf(cm0, __shfl_xor_sync(0xffffffffu, cm0, 1));
            cm0 = fmaxf(cm0, __shfl_xor_sync(0xffffffffu, cm0, 2));
            cm1 = fmaxf(cm1, __shfl_xor_sync(0xffffffffu, cm1, 1));
            cm1 = fmaxf(cm1, __shfl_xor_sync(0xffffffffu, cm1, 2));
            float mn0 = fmaxf(mst[mt][0], cm0);
            float mn1 = fmaxf(mst[mt][1], cm1);
            float r0 = __expf(mst[mt][0] - mn0);
            float r1 = __expf(mst[mt][1] - mn1);
            float s0 = 0.f, s1 = 0.f;
#pragma unroll
            for (int j = 0; j < 8; ++j) {
                Lg[j][0] = __expf(Lg[j][0] - mn0);
                Lg[j][1] = __expf(Lg[j][1] - mn0);
                Lg[j][2] = __expf(Lg[j][2] - mn1);
                Lg[j][3] = __expf(Lg[j][3] - mn1);
                s0 += Lg[j][0] + Lg[j][1];
                s1 += Lg[j][2] + Lg[j][3];
            }
            s0 += __shfl_xor_sync(0xffffffffu, s0, 1);
            s0 += __shfl_xor_sync(0xffffffffu, s0, 2);
            s1 += __shfl_xor_sync(0xffffffffu, s1, 1);
            s1 += __shfl_xor_sync(0xffffffffu, s1, 2);
            lst[mt][0] = lst[mt][0] * r0 + s0;
            lst[mt][1] = lst[mt][1] * r1 + s1;
            mst[mt][0] = mn0; mst[mt][1] = mn1;
#pragma unroll
            for (int j = 0; j < 8; ++j) {
                O[mt][j][0] *= r0; O[mt][j][1] *= r0;
                O[mt][j][2] *= r1; O[mt][j][3] *= r1;
            }
#pragma unroll
            for (int t = 0; t < 4; ++t) {
                uint32_t ph[4], pl[4];
                split_pair(Lg[2 * t][0],     Lg[2 * t][1],     ph[0], pl[0]);
                split_pair(Lg[2 * t][2],     Lg[2 * t][3],     ph[1], pl[1]);
                split_pair(Lg[2 * t + 1][0], Lg[2 * t + 1][1], ph[2], pl[2]);
                split_pair(Lg[2 * t + 1][2], Lg[2 * t + 1][3], ph[3], pl[3]);
#pragma unroll
                for (int nb = 0; nb < 4; ++nb) {
                    uint32_t th[4], tl[4];
                    ldmx4(th, smem_u32(Vh + (nb * 16 + lr) * 72 + t * 16 + lk));
                    ldmx4(tl, smem_u32(Vl + (nb * 16 + lr) * 72 + t * 16 + lk));
                    uint32_t b0h[2] = {th[0], th[2]}, b1h[2] = {th[1], th[3]};
                    uint32_t b0l[2] = {tl[0], tl[2]}, b1l[2] = {tl[1], tl[3]};
                    mma16816(O[mt][nb * 2], ph, b0h);
                    mma16816(O[mt][nb * 2], pl, b0h);
                    mma16816(O[mt][nb * 2], ph, b0l);
                    mma16816(O[mt][nb * 2 + 1], ph, b1h);
                    mma16816(O[mt][nb * 2 + 1], pl, b1h);
                    mma16816(O[mt][nb * 2 + 1], ph, b1l);
                }
            }
        }
    }

    int rr = lane >> 2, cc = (lane & 3) << 1;
    size_t pbase = ((size_t)kc * BH_ + bh) * (M_ * D_);
#pragma unroll
    for (int mt = 0; mt < 2; ++mt) {
        int row = m0 + mt * 16 + rr;
#pragma unroll
        for (int nj = 0; nj < 8; ++nj) {
            int col = nj * 8 + cc;
            *(float2*)(part + pbase + (size_t)row * 64 + col) =
                make_float2(O[mt][nj][0], O[mt][nj][1]);
            *(float2*)(part + pbase + (size_t)(row + 8) * 64 + col) =
                make_float2(O[mt][nj][2], O[mt][nj][3]);
        }
        if ((lane & 3) == 0) {
            size_t sb = ((size_t)kc * BH_ + bh) * M_;
            stats[(sb + row) * 2 + 0] = mst[mt][0];
            stats[(sb + row) * 2 + 1] = lst[mt][0];
            stats[(sb + row + 8) * 2 + 0] = mst[mt][1];
            stats[(sb + row + 8) * 2 + 1] = lst[mt][1];
        }
    }
}

__global__ void avreduce2_kernel(const float* __restrict__ part,
                                 const float* __restrict__ stats,
                                 float* __restrict__ av)
{
    int bh = blockIdx.x >> 8;
    int row = blockIdx.x & 255;
    int d = threadIdx.x;
    float M = -1e30f;
#pragma unroll
    for (int c = 0; c < 8; ++c)
        M = fmaxf(M, stats[(((size_t)c * BH_ + bh) * M_ + row) * 2]);
    float lt = 0.f, acc = 0.f;
#pragma unroll
    for (int c = 0; c < 8; ++c) {
        size_t sb = ((size_t)c * BH_ + bh) * M_ + row;
        float w = __expf(stats[sb * 2] - M);
        lt += w * stats[sb * 2 + 1];
        acc += w * part[(((size_t)c * BH_ + bh) * M_ + row) * 64 + d];
    }
    av[((size_t)bh * M_ + row) * 64 + d] = acc / lt;
}

// ======================= fused attn1 -> (+conv) pre ============================
// R17: adds its output into pre[(b*N+i)*512 + h*64 + col] (conv residual
// already written there by conv_kernel). outh eliminated.
#define F1_SMEM 178176
__global__ void __launch_bounds__(256) fattn1_kernel(
    const float* __restrict__ qkv, const float* __restrict__ kL,
    const float* __restrict__ Wz, float* __restrict__ pre)
{
    extern __shared__ char sm1[];
    __nv_bfloat16* Qh = (__nv_bfloat16*)sm1;               // [128][72]
    __nv_bfloat16* Ql = Qh + 128 * 72;
    __nv_bfloat16* Kh = (__nv_bfloat16*)(sm1 + 36864);     // [256][72]
    __nv_bfloat16* Kl = Kh + 256 * 72;
    __nv_bfloat16* Wh = (__nv_bfloat16*)(sm1 + 36864 + 73728); // [64][264]
    __nv_bfloat16* Wl = Wh + 64 * 264;

    int tid = threadIdx.x, lane = tid & 31, wid = tid >> 5;
    int bh = blockIdx.x;
    int b = bh >> 3, h = bh & 7;
    int i0base = blockIdx.y << 8;
    int lr = lane & 15, lk = (lane >> 4) << 3;

#pragma unroll
    for (int j = 0; j < 16; ++j) {
        int v = tid + (j << 8);
        int rr = v >> 4, c4 = (v & 15) << 2;
        float4 f = *(const float4*)(kL + (size_t)bh * 16384 + rr * 64 + c4);
        uint2 hi, lo; cvt_split4(f, hi, lo);
        *(uint2*)(Kh + rr * 72 + c4) = hi;
        *(uint2*)(Kl + rr * 72 + c4) = lo;
    }
#pragma unroll
    for (int j = 0; j < 16; ++j) {
        int v = tid + (j << 8);
        int k = v >> 4, n4 = (v & 15) << 2;
        float4 f = *(const float4*)(Wz + (size_t)bh * 16384 + k * 64 + n4);
        float e[4] = {f.x, f.y, f.z, f.w};
#pragma unroll
        for (int q = 0; q < 4; ++q) {
            __nv_bfloat16 hv = __float2bfloat16(e[q]);
            Wh[(n4 + q) * 264 + k] = hv;
            Wl[(n4 + q) * 264 + k] = __float2bfloat16(e[q] - __bfloat162float(hv));
        }
    }

    for (int rblk = 0; rblk < 2; ++rblk) {
        int i0 = i0base + (rblk << 7);
        __syncthreads();
#pragma unroll
        for (int j = 0; j < 8; ++j) {
            int v = tid + (j << 8);
            int rr = v >> 4, c4 = (v & 15) << 2;
            float4 f = *(const float4*)(qkv + (size_t)(b * N_ + i0 + rr) * LDQKV + h * 64 + c4);
            f.x *= 0.125f; f.y *= 0.125f; f.z *= 0.125f; f.w *= 0.125f;
            uint2 hi, lo; cvt_split4(f, hi, lo);
            *(uint2*)(Qh + rr * 72 + c4) = hi;
            *(uint2*)(Ql + rr * 72 + c4) = lo;
        }
        __syncthreads();

        int m0 = wid << 4;
        float Lg[32][4];
#pragma unroll
        for (int j = 0; j < 32; ++j)
#pragma unroll
            for (int q = 0; q < 4; ++q) Lg[j][q] = 0.f;

#pragma unroll
        for (int ksx = 0; ksx < 4; ++ksx) {
            uint32_t qh[4], ql[4];
            ldmx4(qh, smem_u32(Qh + (m0 + lr) * 72 + ksx * 16 + lk));
            ldmx4(ql, smem_u32(Ql + (m0 + lr) * 72 + ksx * 16 + lk));
#pragma unroll
            for (int nb = 0; nb < 16; ++nb) {
                uint32_t th[4], tl[4];
                ldmx4(th, smem_u32(Kh + (nb * 16 + lr) * 72 + ksx * 16 + lk));
                ldmx4(tl, smem_u32(Kl + (nb * 16 + lr) * 72 + ksx * 16 + lk));
                uint32_t b0h[2] = {th[0], th[2]}, b1h[2] = {th[1], th[3]};
                uint32_t b0l[2] = {tl[0], tl[2]}, b1l[2] = {tl[1], tl[3]};
                mma16816(Lg[nb * 2], qh, b0h);
                mma16816(Lg[nb * 2], ql, b0h);
                mma16816(Lg[nb * 2], qh, b0l);
                mma16816(Lg[nb * 2 + 1], qh, b1h);
                mma16816(Lg[nb * 2 + 1], ql, b1h);
                mma16816(Lg[nb * 2 + 1], qh, b1l);
            }
        }

        float mx0 = -1e30f, mx1 = -1e30f;
#pragma unroll
        for (int j = 0; j < 32; ++j) {
            mx0 = fmaxf(mx0, fmaxf(Lg[j][0], Lg[j][1]));
            mx1 = fmaxf(mx1, fmaxf(Lg[j][2], Lg[j][3]));
        }
        mx0 = fmaxf(mx0, __shfl_xor_sync(0xffffffffu, mx0, 1));
        mx0 = fmaxf(mx0, __shfl_xor_sync(0xffffffffu, mx0, 2));
        mx1 = fmaxf(mx1, __shfl_xor_sync(0xffffffffu, mx1, 1));
        mx1 = fmaxf(mx1, __shfl_xor_sync(0xffffffffu, mx1, 2));
        float s0 = 0.f, s1 = 0.f;
#pragma unroll
        for (int j = 0; j < 32; ++j) {
            Lg[j][0] = __expf(Lg[j][0] - mx0);
            Lg[j][1] = __expf(Lg[j][1] - mx0);
            Lg[j][2] = __expf(Lg[j][2] - mx1);
            Lg[j][3] = __expf(Lg[j][3] - mx1);
            s0 += Lg[j][0] + Lg[j][1];
            s1 += Lg[j][2] + Lg[j][3];
        }
        s0 += __shfl_xor_sync(0xffffffffu, s0, 1);
        s0 += __shfl_xor_sync(0xffffffffu, s0, 2);
        s1 += __shfl_xor_sync(0xffffffffu, s1, 1);
        s1 += __shfl_xor_sync(0xffffffffu, s1, 2);
        float inv0 = 1.f / s0, inv1 = 1.f / s1;

        float O[8][4];
#pragma unroll
        for (int j = 0; j < 8; ++j)
#pragma unroll
            for (int q = 0; q < 4; ++q) O[j][q] = 0.f;

#pragma unroll
        for (int t = 0; t < 16; ++t) {
            uint32_t ph[4], pl[4];
            split_pair(Lg[2 * t][0] * inv0,     Lg[2 * t][1] * inv0,     ph[0], pl[0]);
            split_pair(Lg[2 * t][2] * inv1,     Lg[2 * t][3] * inv1,     ph[1], pl[1]);
            split_pair(Lg[2 * t + 1][0] * inv0, Lg[2 * t + 1][1] * inv0, ph[2], pl[2]);
            split_pair(Lg[2 * t + 1][2] * inv1, Lg[2 * t + 1][3] * inv1, ph[3], pl[3]);
#pragma unroll
            for (int nb = 0; nb < 4; ++nb) {
                uint32_t th[4], tl[4];
                ldmx4(th, smem_u32(Wh + (nb * 16 + lr) * 264 + t * 16 + lk));
                ldmx4(tl, smem_u32(Wl + (nb * 16 + lr) * 264 + t * 16 + lk));
                uint32_t b0h[2] = {th[0], th[2]}, b1h[2] = {th[1], th[3]};
                uint32_t b0l[2] = {tl[0], tl[2]}, b1l[2] = {tl[1], tl[3]};
                mma16816(O[nb * 2], ph, b0h);
                mma16816(O[nb * 2], pl, b0h);
                mma16816(O[nb * 2], ph, b0l);
                mma16816(O[nb * 2 + 1], ph, b1h);
                mma16816(O[nb * 2 + 1], pl, b1h);
                mma16816(O[nb * 2 + 1], ph, b1l);
            }
        }

        // add into pre (conv residual already there): token-major layout
        int rr = lane >> 2, cc = (lane & 3) << 1;
        size_t tok = (size_t)b * N_ + i0 + m0;
#pragma unroll
        for (int nj = 0; nj < 8; ++nj) {
            int col = nj * 8 + cc;
            float* p0 = pre + (tok + rr) * DIM_ + h * D_ + col;
            float* p1 = pre + (tok + rr + 8) * DIM_ + h * D_ + col;
            float2 o0 = *(float2*)p0, o1 = *(float2*)p1;
            *(float2*)p0 = make_float2(o0.x + O[nj][0], o0.y + O[nj][1]);
            *(float2*)p1 = make_float2(o1.x + O[nj][2], o1.y + O[nj][3]);
        }
    }
}

// ---------------- landmarks ---------------------------------------------------
__global__ void landmarks_kernel(const float* __restrict__ qkv,
                                 float* __restrict__ qL, float* __restrict__ kL)
{
    int bh = blockIdx.x >> 8;
    int lm = blockIdx.x & 255;
    int b = bh >> 3, h = bh & 7;
    int d = threadIdx.x;
    long long base = ((long long)(b * N_ + lm * L_)) * LDQKV + h * D_ + d;
    float sq = 0.f, sk = 0.f;
#pragma unroll 4
    for (int t = 0; t < L_; t++) {
        sq += qkv[base + (long long)t * LDQKV];
        sk += qkv[base + (long long)t * LDQKV + 512];
    }
    long long o = ((long long)bh * M_ + lm) * D_ + d;
    qL[o] = sq * (0.125f / (float)L_);
    kL[o] = sk * (1.0f / (float)L_);
}

// ---------------- softmax (row length 256) — shuffle reduction ----------------
__global__ void softmax256_kernel(float* __restrict__ data)
{
    __shared__ float redm[8], reds[8];
    long long row = blockIdx.x;
    float* p = data + row * 256;
    int t = threadIdx.x, lane = t & 31, w = t >> 5;
    float v = p[t];
    float m = v;
#pragma unroll
    for (int o = 16; o > 0; o >>= 1) m = fmaxf(m, __shfl_xor_sync(0xffffffffu, m, o));
    if (lane == 0) redm[w] = m;
    __syncthreads();
    float M = redm[0];
#pragma unroll
    for (int i = 1; i < 8; ++i) M = fmaxf(M, redm[i]);
    float e = __expf(v - M);
    float s = e;
#pragma unroll
    for (int o = 16; o > 0; o >>= 1) s += __shfl_xor_sync(0xffffffffu, s, o);
    if (lane == 0) reds[w] = s;
    __syncthreads();
    float S = reds[0];
#pragma unroll
    for (int i = 1; i < 8; ++i) S += reds[i];
    p[t] = e * (1.f / S);
}

// ---------------- pinv init ------------------------------------------------------
__global__ void init_bits_kernel(unsigned int* bits)
{
    if (threadIdx.x == 0) { bits[0] = __float_as_uint(1.0f); g_barc = 0u; }
    else bits[1] = 0u;
}

__global__ void colmax_kernel(const float* __restrict__ a, unsigned int* bits)
{
    __shared__ float red[256];
    int bb = blockIdx.x >> 8, j = blockIdx.x & 255;
    int t = threadIdx.x;
    red[t] = fabsf(a[((long long)bb << 16) + ((long long)t << 8) + j]);
    __syncthreads();
    for (int s = 128; s > 0; s >>= 1) { if (t < s) red[t] += red[t + s]; __syncthreads(); }
    if (t == 0) atomicMax(bits + 1, __float_as_uint(red[0]));
}

__global__ void zinit_kernel(const float* __restrict__ a, float* __restrict__ z,
                             const unsigned int* __restrict__ bits)
{
    float denom = __uint_as_float(bits[0]) * __uint_as_float(bits[1]) + 1e-12f;
    float inv = 1.f / denom;
    long long idx = (long long)blockIdx.x * 256 + threadIdx.x;
    long long bb = idx >> 16;
    int r = (int)(idx >> 8) & 255;
    int c = (int)idx & 255;
    z[idx] = a[(bb << 16) + ((long long)c << 8) + r] * inv;
}

// ---------------- depthwise conv residual (rolling FIR) -> pre -----------------
#define CCH 256
__global__ void __launch_bounds__(256) conv_kernel(
    const float* __restrict__ qkv, const float* __restrict__ convw,
    float* __restrict__ pre)
{
    int blk = blockIdx.x;
    int chunk = blk & 31;
    int hhalf = (blk >> 5) & 1;
    int b = blk >> 6;
    int h = hhalf * 4 + (threadIdx.x >> 6);
    int d = threadIdx.x & 63;
    int i0 = chunk * CCH;

    float cw[33];
#pragma unroll
    for (int t = 0; t < 33; ++t) cw[t] = convw[h * 33 + t];

    const float* vcol = qkv + 1024 + h * D_ + d;
    float w[33];
#pragma unroll
    for (int t = 0; t < 33; ++t) {
        int ii = i0 - 16 + t;
        w[t] = (ii >= 0 && ii < N_) ? vcol[(size_t)(b * N_ + ii) * LDQKV] : 0.f;
    }

    float* prow = pre + ((size_t)(b * N_ + i0)) * DIM_ + h * D_ + d;

    for (int i = 0; i < CCH; ++i) {
        float s = 0.f;
#pragma unroll
        for (int t = 0; t < 33; ++t) s += cw[t] * w[t];
        prow[(size_t)i * DIM_] = s;
#pragma unroll
        for (int t = 0; t < 32; ++t) w[t] = w[t + 1];
        int ii = i0 + i + 17;
        w[32] = (ii >= 0 && ii < N_) ? vcol[(size_t)(b * N_ + ii) * LDQKV] : 0.f;
    }
}

// ---------------- host side -----------------------------------------------------
struct GArgs {
    const float *A, *B; float* C; const float* bias;
    int lda, ldb, ldc;
    long long aO, aI, bO, bI, cO, cI;
    int transB, bmode; float alphaB, scale;
    int kchunks, klen; long long csplit;
    const __nv_bfloat16* B16h; const __nv_bfloat16* B16l;
};

template<int BN, int NTRM, int BF16B>
static inline void launch_bgemm(int M, int N, int batches, const GArgs& g, cudaStream_t st)
{
    constexpr int TERMS = (NTRM == 3) ? 2 : 1;
    const size_t smem = 2ull * TERMS * (128 + BN) * SPAD * sizeof(__nv_bfloat16);
    static bool attr_set = false;
    if (!attr_set) {
        cudaFuncSetAttribute(bgemm_kernel<BN, NTRM, BF16B>,
                             cudaFuncAttributeMaxDynamicSharedMemorySize, (int)smem);
        attr_set = true;
    }
    dim3 grid(N / BN, (M / 128) * g.kchunks, batches);
    bgemm_kernel<BN, NTRM, BF16B><<<grid, 256, smem, st>>>(
        g.A, g.B, g.B16h, g.B16l, g.C, g.bias, g.lda, g.ldb, g.ldc,
        g.aO, g.aI, g.bO, g.bI, g.cO, g.cI,
        g.transB, g.bmode, g.alphaB, g.scale,
        g.kchunks, g.klen, g.csplit);
}

extern "C" void kernel_launch(void* const* d_in, const int* in_sizes, int n_in,
                              void* d_out, int out_size)
{
    const float* x     = (const float*)d_in[0];
    const float* Wqkv  = (const float*)d_in[1];
    const float* Wout  = (const float*)d_in[2];
    const float* bout  = (const float*)d_in[3];
    const float* convw = (const float*)d_in[4];
    float* out = (float*)d_out;

    float *qkv, *qL, *kL, *attn2, *z0, *z1, *xz, *t2, *t3, *av, *W, *pre;
    float *avpart, *avstats;
    __nv_bfloat16 *wqh, *wql, *woh, *wol;
    unsigned int* bits;
    cudaGetSymbolAddress((void**)&qkv,    g_qkv);
    cudaGetSymbolAddress((void**)&qL,     g_qL);
    cudaGetSymbolAddress((void**)&kL,     g_kL);
    cudaGetSymbolAddress((void**)&attn2,  g_attn2);
    cudaGetSymbolAddress((void**)&z0,     g_z0);
    cudaGetSymbolAddress((void**)&z1,     g_z1);
    cudaGetSymbolAddress((void**)&xz,     g_xz);
    cudaGetSymbolAddress((void**)&t2,     g_t2);
    cudaGetSymbolAddress((void**)&t3,     g_t3);
    cudaGetSymbolAddress((void**)&av,     g_av);
    cudaGetSymbolAddress((void**)&W,      g_W);
    cudaGetSymbolAddress((void**)&pre,    g_pre);
    cudaGetSymbolAddress((void**)&avpart, g_avpart);
    cudaGetSymbolAddress((void**)&avstats,g_avstats);
    cudaGetSymbolAddress((void**)&wqh,    g_wqh);
    cudaGetSymbolAddress((void**)&wql,    g_wql);
    cudaGetSymbolAddress((void**)&woh,    g_woh);
    cudaGetSymbolAddress((void**)&wol,    g_wol);
    cudaGetSymbolAddress((void**)&bits,   g_bits);

    cudaFuncSetAttribute(fattn3_kernel, cudaFuncAttributeMaxDynamicSharedMemorySize, F3_SMEM);
    cudaFuncSetAttribute(fattn1_kernel, cudaFuncAttributeMaxDynamicSharedMemorySize, F1_SMEM);

    static cudaStream_t s1 = nullptr, s2 = nullptr;
    static cudaEvent_t ev_land = nullptr, ev_z = nullptr, ev_qkv = nullptr, ev_conv = nullptr;
    if (!s1) {
        cudaStreamCreateWithFlags(&s1, cudaStreamNonBlocking);
        cudaStreamCreateWithFlags(&s2, cudaStreamNonBlocking);
        cudaEventCreateWithFlags(&ev_land, cudaEventDisableTiming);
        cudaEventCreateWithFlags(&ev_z, cudaEventDisableTiming);
        cudaEventCreateWithFlags(&ev_qkv, cudaEventDisableTiming);
        cudaEventCreateWithFlags(&ev_conv, cudaEventDisableTiming);
    }
    cudaStream_t s0 = 0;

    const long long MM = (long long)M_ * M_;
    const long long MD = (long long)M_ * D_;

    // 0) weight splits: Wqkv on s0 (needed by qkv), Wout on s2
    wsplit_kernel<<<(1536 * 512 + 255) / 256, 256, 0, s0>>>(Wqkv, wqh, wql, 512, 1536);
    wsplit_kernel<<<(512 * 512 + 255) / 256, 256, 0, s2>>>(Wout, woh, wol, 512, 512);

    // 1) qkv = x @ Wqkv  (BF16B pre-split weights)  [s0]
    { GArgs g{x, nullptr, qkv, nullptr, 512, 512, LDQKV,
              0,0, 0,0, 0,0, 0, 0, 0.f, 1.f, 1, 512, 0, wqh, wql};
      launch_bgemm<128, 3, 1>(NT_, 1536, 1, g, s0); }
    cudaEventRecord(ev_qkv, s0);

    // conv residual -> pre on s2 (needs qkv only; overlaps everything)
    cudaStreamWaitEvent(s2, ev_qkv, 0);
    conv_kernel<<<B_ * 2 * (N_ / CCH), 256, 0, s2>>>(qkv, convw, pre);
    cudaEventRecord(ev_conv, s2);

    // 2) landmarks                 [s0]
    landmarks_kernel<<<BH_ * M_, 64, 0, s0>>>(qkv, qL, kL);
    cudaEventRecord(ev_land, s0);

    // ---- fork: pinv branch on s1 ----
    cudaStreamWaitEvent(s1, ev_land, 0);

    { GArgs g{qL, kL, attn2, nullptr, 64, 64, M_,
              8*MD, MD, 8*MD, MD, 8*MM, MM, 1, 0, 0.f, 1.f, 1, 64, 0, nullptr, nullptr};
      launch_bgemm<64, 3, 0>(M_, M_, BH_, g, s1); }
    softmax256_kernel<<<BH_ * M_, 256, 0, s1>>>(attn2);

    init_bits_kernel<<<1, 2, 0, s1>>>(bits);
    colmax_kernel<<<BH_ * M_, 256, 0, s1>>>(attn2, bits);
    zinit_kernel<<<BH_ * M_, 256, 0, s1>>>(attn2, z0, bits);

    pinv_kernel<<<256, 256, 0, s1>>>(attn2, z0, z1, xz, t2, t3);
    cudaEventRecord(ev_z, s1);

    // ---- meanwhile on s0: fused attn3 -> av ----
    { dim3 grid(BH_, 8);
      fattn3_kernel<<<grid, 256, F3_SMEM, s0>>>(qkv, qL, avpart, avstats); }
    avreduce2_kernel<<<BH_ * M_, 64, 0, s0>>>(avpart, avstats, av);

    // ---- join ----
    cudaStreamWaitEvent(s0, ev_z, 0);

    // W = z @ av
    { GArgs g{z0, av, W, nullptr, M_, D_, D_,
              8*MM, MM, 8*MD, MD, 8*MD, MD, 0, 0, 0.f, 1.f, 1, M_, 0, nullptr, nullptr};
      launch_bgemm<64, 3, 0>(M_, D_, BH_, g, s0); }

    // fattn1 adds into pre (needs conv residual)
    cudaStreamWaitEvent(s0, ev_conv, 0);
    { dim3 grid(BH_, N_ / 256);
      fattn1_kernel<<<grid, 256, F1_SMEM, s0>>>(qkv, kL, W, pre); }

    // out = pre @ Wout + bout (BF16B pre-split weights)
    { GArgs g{pre, nullptr, out, bout, DIM_, DIM_, DIM_,
              0,0, 0,0, 0,0, 0, 0, 0.f, 1.f, 1, DIM_, 0, woh, wol};
      launch_bgemm<128, 3, 1>(NT_, DIM_, 1, g, s0); }
}